// round 4
// baseline (speedup 1.0000x reference)
#include <cuda_runtime.h>
#include <cuda_bf16.h>

// Problem constants (TRIP log_prob): B=32768, M=8, D=256, R=32
#define MM 8
#define DD 256
#define RR 32
#define TB 16          // batch elements per block
#define NTHREADS 512   // 16 warps

#define LOG_2PI_F 1.8378770664093453f

// Scratch: softplus(cores), per-mode core sums, log(trace(norm))
__device__ float g_spc[MM * DD * RR * RR];   // 8 MB
__device__ float g_s[MM * RR * RR];          // 32 KB
__device__ float g_lognorm;

// ---------------- f32x2 packed helpers (sm_100+) ----------------
__device__ __forceinline__ unsigned long long splat2(float x) {
    unsigned long long r;
    asm("mov.b64 %0, {%1, %1};" : "=l"(r) : "f"(x));
    return r;
}
__device__ __forceinline__ unsigned long long pack2(float lo, float hi) {
    unsigned long long r;
    asm("mov.b64 %0, {%1, %2};" : "=l"(r) : "f"(lo), "f"(hi));
    return r;
}
__device__ __forceinline__ void fma2(unsigned long long& acc,
                                     unsigned long long a,
                                     unsigned long long b) {
    asm("fma.rn.f32x2 %0, %1, %2, %0;" : "+l"(acc) : "l"(a), "l"(b));
}

// ---------------- kernel 0: softplus(cores) ----------------
__global__ void k_softplus(const float* __restrict__ cores) {
    int i = blockIdx.x * blockDim.x + threadIdx.x;  // exactly 2,097,152 threads
    float x = cores[i];
    float sp = (x > 20.0f) ? x : log1pf(expf(x));
    g_spc[i] = sp;
}

// ---------------- kernel 1: per-mode core sums s_i[j,k] = sum_d spc ----------------
__global__ void k_modesum() {  // grid = MM blocks, 1024 threads
    int i = blockIdx.x;
    int t = threadIdx.x;  // (j,k) flat
    float a = 0.0f;
    const float* base = g_spc + (size_t)i * DD * RR * RR + t;
    #pragma unroll 4
    for (int d = 0; d < DD; ++d) a += base[d * (RR * RR)];
    g_s[i * RR * RR + t] = a;
}

// ---------------- kernel 2: norm chain + log(trace) ----------------
__global__ void k_normchain() {  // 1 block, 1024 threads
    __shared__ float nrm[RR * RR];
    __shared__ float s[RR * RR];
    __shared__ float tmp[RR * RR];
    int t = threadIdx.x;
    int r = t >> 5, c = t & 31;
    nrm[t] = g_s[t];
    __syncthreads();
    for (int i = 1; i < MM; ++i) {
        s[t] = g_s[i * RR * RR + t];
        __syncthreads();
        float a = 0.0f;
        #pragma unroll
        for (int j = 0; j < RR; ++j) a += nrm[r * RR + j] * s[j * RR + c];
        tmp[t] = a;
        __syncthreads();
        nrm[t] = tmp[t];
        __syncthreads();
    }
    if (t == 0) {
        float tr = 0.0f;
        #pragma unroll
        for (int k = 0; k < RR; ++k) tr += nrm[k * (RR + 1)];
        g_lognorm = logf(tr);
    }
}

// ---------------- main fused kernel ----------------
// Dynamic smem layout:
//   PU   : unsigned long long [DD][TB]        (p splatted to (p,p))  32768 B
//   MARG : float [TB][RR][RR]                                        65536 B
//   S    : float [TB][RR][36]  (state transposed: S[b][j][r]=prob[r][j],
//                               row stride 36 floats for bank-conflict-free)
//                                                                     73728 B
#define SMEM_PU    0
#define SMEM_MARG  32768
#define SMEM_S     (32768 + 65536)
#define SMEM_TOTAL (32768 + 65536 + 73728)
#define S_STRIDE   36

__global__ void __launch_bounds__(NTHREADS, 1)
k_trip_main(const float* __restrict__ value,
            const float* __restrict__ location,
            const float* __restrict__ log_scale,
            float* __restrict__ out) {
    extern __shared__ unsigned char smem_raw[];
    unsigned long long* PU = reinterpret_cast<unsigned long long*>(smem_raw + SMEM_PU);
    float* MARG = reinterpret_cast<float*>(smem_raw + SMEM_MARG);
    float* S = reinterpret_cast<float*>(smem_raw + SMEM_S);

    const int tid = threadIdx.x;
    const int bblk = blockIdx.x * TB;

    for (int mode = 0; mode < MM; ++mode) {
        // ---- phase 1: Gaussian weights p[d][b], pre-splatted ----
        {
            const int d = tid >> 1;       // 0..255
            const int half = tid & 1;     // b group 0..7 / 8..15
            const float li  = __ldg(&location[d * MM + mode]);
            const float lsi = __ldg(&log_scale[d * MM + mode]);
            const float inv = __expf(-lsi);
            const float cbase = -0.5f * LOG_2PI_F - lsi;
            #pragma unroll
            for (int b = 0; b < 8; ++b) {
                const int bg = bblk + half * 8 + b;
                const float v = __ldg(&value[bg * MM + mode]);
                const float z = (v - li) * inv;
                const float pv = __expf(fmaf(-0.5f * z, z, cbase));
                PU[d * TB + half * 8 + b] = splat2(pv);
            }
        }
        __syncthreads();

        // ---- phase 2: margins  marg[b][j][c] = sum_d p[b][d] * C[d][j][c] ----
        {
            const int j  = tid >> 4;   // 0..31
            const int cp = tid & 15;   // c-pair 0..15 (c = 2cp, 2cp+1)
            const float2* __restrict__ cptr =
                reinterpret_cast<const float2*>(g_spc) +
                (size_t)mode * (DD * RR * RR / 2) + j * (RR / 2) + cp;

            unsigned long long acc[TB];
            #pragma unroll
            for (int b = 0; b < TB; ++b) acc[b] = 0ull;

            float2 cbuf[8];
            #pragma unroll
            for (int k = 0; k < 8; ++k) cbuf[k] = __ldg(cptr + k * (RR * RR / 2));

            for (int d0 = 0; d0 < DD; d0 += 8) {
                float2 nbuf[8];
                if (d0 + 8 < DD) {
                    #pragma unroll
                    for (int k = 0; k < 8; ++k)
                        nbuf[k] = __ldg(cptr + (size_t)(d0 + 8 + k) * (RR * RR / 2));
                }
                #pragma unroll
                for (int k = 0; k < 8; ++k) {
                    const int d = d0 + k;
                    const unsigned long long c01 = pack2(cbuf[k].x, cbuf[k].y);
                    const ulonglong2* prow =
                        reinterpret_cast<const ulonglong2*>(PU + d * TB);
                    #pragma unroll
                    for (int bp = 0; bp < TB / 2; ++bp) {
                        ulonglong2 pp = prow[bp];
                        fma2(acc[2 * bp], pp.x, c01);
                        fma2(acc[2 * bp + 1], pp.y, c01);
                    }
                }
                #pragma unroll
                for (int k = 0; k < 8; ++k) cbuf[k] = nbuf[k];
            }

            unsigned long long* mdst = reinterpret_cast<unsigned long long*>(MARG);
            #pragma unroll
            for (int b = 0; b < TB; ++b)
                mdst[b * (RR * RR / 2) + j * (RR / 2) + cp] = acc[b];
        }
        __syncthreads();

        // ---- phase 3: chain  prob <- prob @ margin  (state transposed in S) ----
        {
            const int bb = tid >> 5;  // batch within block (warp)
            const int c = tid & 31;   // output column (lane)
            if (mode == 0) {
                // S[bb][c][r] = marg[bb][r][c]  (prob = margin)
                float4 rowv[8];
                #pragma unroll
                for (int k = 0; k < 8; ++k) {
                    rowv[k].x = MARG[bb * 1024 + (4 * k + 0) * RR + c];
                    rowv[k].y = MARG[bb * 1024 + (4 * k + 1) * RR + c];
                    rowv[k].z = MARG[bb * 1024 + (4 * k + 2) * RR + c];
                    rowv[k].w = MARG[bb * 1024 + (4 * k + 3) * RR + c];
                }
                __syncthreads();
                float4* dst = reinterpret_cast<float4*>(S + bb * (RR * S_STRIDE) + c * S_STRIDE);
                #pragma unroll
                for (int k = 0; k < 8; ++k) dst[k] = rowv[k];
            } else {
                float m[RR];
                #pragma unroll
                for (int j = 0; j < RR; ++j) m[j] = MARG[bb * 1024 + j * RR + c];

                unsigned long long acc[16];
                #pragma unroll
                for (int k = 0; k < 16; ++k) acc[k] = 0ull;

                #pragma unroll
                for (int j = 0; j < RR; ++j) {
                    const unsigned long long mm = splat2(m[j]);
                    const ulonglong2* srow = reinterpret_cast<const ulonglong2*>(
                        S + bb * (RR * S_STRIDE) + j * S_STRIDE);
                    #pragma unroll
                    for (int k = 0; k < 8; ++k) {
                        ulonglong2 sv = srow[k];
                        fma2(acc[2 * k], sv.x, mm);      // rows 4k, 4k+1
                        fma2(acc[2 * k + 1], sv.y, mm);  // rows 4k+2, 4k+3
                    }
                }
                __syncthreads();  // all S reads complete before overwrite
                ulonglong2* dst = reinterpret_cast<ulonglong2*>(
                    S + bb * (RR * S_STRIDE) + c * S_STRIDE);
                #pragma unroll
                for (int k = 0; k < 8; ++k) {
                    ulonglong2 v;
                    v.x = acc[2 * k];
                    v.y = acc[2 * k + 1];
                    dst[k] = v;
                }
            }
        }
        __syncthreads();
    }

    // ---- epilogue: trace + log ----
    {
        const int bb = tid >> 5;
        const int lane = tid & 31;
        float dv = S[bb * (RR * S_STRIDE) + lane * S_STRIDE + lane];  // prob[lane][lane]
        #pragma unroll
        for (int o = 16; o > 0; o >>= 1) dv += __shfl_xor_sync(0xffffffffu, dv, o);
        if (lane == 0) {
            out[bblk + bb] = logf(fmaxf(dv, 1e-12f)) - g_lognorm;
        }
    }
}

extern "C" void kernel_launch(void* const* d_in, const int* in_sizes, int n_in,
                              void* d_out, int out_size) {
    const float* value     = (const float*)d_in[0];  // (B, M)
    const float* location  = (const float*)d_in[1];  // (D, M)
    const float* log_scale = (const float*)d_in[2];  // (D, M)
    const float* cores     = (const float*)d_in[3];  // (M, D, R, R)
    float* out = (float*)d_out;

    const int B = in_sizes[0] / MM;
    const int total_core = MM * DD * RR * RR;  // 2,097,152

    k_softplus<<<total_core / 1024, 1024>>>(cores);
    k_modesum<<<MM, 1024>>>();
    k_normchain<<<1, 1024>>>();

    cudaFuncSetAttribute(k_trip_main,
                         cudaFuncAttributeMaxDynamicSharedMemorySize, SMEM_TOTAL);
    k_trip_main<<<B / TB, NTHREADS, SMEM_TOTAL>>>(value, location, log_scale, out);
}

// round 5
// speedup vs baseline: 1.6928x; 1.6928x over previous
#include <cuda_runtime.h>
#include <cuda_bf16.h>

// Problem constants (TRIP log_prob): B=32768, M=8, D=256, R=32
#define MM 8
#define DD 256
#define RR 32
#define TB 16          // batch elements per block
#define NTHREADS 512   // 16 warps

#define LOG_2PI_F 1.8378770664093453f

// Scratch: permuted softplus(cores), per-mode core sums, log(trace(norm))
// Permuted layout: g_spc[mode][d][j][ch][s] where original c = ch + 8*s
// (ch in 0..7, s in 0..3). Permutation is within each 32-float row.
__device__ float g_spc[MM * DD * RR * RR];   // 8 MB
__device__ float g_s[MM * RR * RR];          // 32 KB (natural layout)
__device__ float g_lognorm;

// ---------------- f32x2 packed helpers (sm_100+) ----------------
__device__ __forceinline__ unsigned long long splat2(float x) {
    unsigned long long r;
    asm("mov.b64 %0, {%1, %1};" : "=l"(r) : "f"(x));
    return r;
}
__device__ __forceinline__ unsigned long long pack2(float lo, float hi) {
    unsigned long long r;
    asm("mov.b64 %0, {%1, %2};" : "=l"(r) : "f"(lo), "f"(hi));
    return r;
}
__device__ __forceinline__ void unpack2(unsigned long long v, float& lo, float& hi) {
    asm("mov.b64 {%0, %1}, %2;" : "=f"(lo), "=f"(hi) : "l"(v));
}
__device__ __forceinline__ void fma2(unsigned long long& acc,
                                     unsigned long long a,
                                     unsigned long long b) {
    asm("fma.rn.f32x2 %0, %1, %2, %0;" : "+l"(acc) : "l"(a), "l"(b));
}

// ---------------- kernel 0: softplus(cores) with column permutation ----------------
__global__ void k_softplus(const float* __restrict__ cores) {
    int i = blockIdx.x * blockDim.x + threadIdx.x;  // 2,097,152 threads
    float x = cores[i];
    float sp = (x > 20.0f) ? x : log1pf(expf(x));
    int c = i & 31;
    int ch = c & 7;
    int s = c >> 3;
    int row = i >> 5;                       // (mode,d,j) flat
    g_spc[(row << 5) + ch * 4 + s] = sp;    // permuted within row
}

// ---------------- kernel 1: per-mode core sums (un-permute into natural) ----------------
__global__ void k_modesum() {  // grid = MM blocks, 1024 threads
    int i = blockIdx.x;
    int t = threadIdx.x;  // permuted (j, pos) flat: pos = ch*4+s
    float a = 0.0f;
    const float* base = g_spc + (size_t)i * DD * RR * RR + t;
    #pragma unroll 4
    for (int d = 0; d < DD; ++d) a += base[d * (RR * RR)];
    int pos = t & 31;
    int j = t >> 5;
    int ch = pos >> 2;
    int s = pos & 3;
    int c = ch + 8 * s;                     // natural column
    g_s[i * RR * RR + j * RR + c] = a;
}

// ---------------- kernel 2: norm chain + log(trace) ----------------
__global__ void k_normchain() {  // 1 block, 1024 threads
    __shared__ float nrm[RR * RR];
    __shared__ float s[RR * RR];
    __shared__ float tmp[RR * RR];
    int t = threadIdx.x;
    int r = t >> 5, c = t & 31;
    nrm[t] = g_s[t];
    __syncthreads();
    for (int i = 1; i < MM; ++i) {
        s[t] = g_s[i * RR * RR + t];
        __syncthreads();
        float a = 0.0f;
        #pragma unroll
        for (int j = 0; j < RR; ++j) a += nrm[r * RR + j] * s[j * RR + c];
        tmp[t] = a;
        __syncthreads();
        nrm[t] = tmp[t];
        __syncthreads();
    }
    if (t == 0) {
        float tr = 0.0f;
        #pragma unroll
        for (int k = 0; k < RR; ++k) tr += nrm[k * (RR + 1)];
        g_lognorm = logf(tr);
    }
}

// ---------------- main fused kernel ----------------
// Dynamic smem layout:
//   PP : ulonglong [DD][8]   p batch-pairs (p_2bp, p_2bp+1), NOT splatted  16384 B
//   MG : ulonglong [8][RR*RR] margin batch-pairs: MG[bp][j*32+c]           65536 B
//   S  : float [TB][RR][36]  state transposed: S[b][c][r] = prob[r][c]     73728 B
#define SM_PP   0
#define SM_MG   16384
#define SM_S    (16384 + 65536)
#define SMEM_TOTAL (16384 + 65536 + 73728)
#define S_STRIDE 36

__global__ void __launch_bounds__(NTHREADS, 1)
k_trip_main(const float* __restrict__ value,
            const float* __restrict__ location,
            const float* __restrict__ log_scale,
            float* __restrict__ out) {
    extern __shared__ unsigned char smem_raw[];
    unsigned long long* PP = reinterpret_cast<unsigned long long*>(smem_raw + SM_PP);
    unsigned long long* MG = reinterpret_cast<unsigned long long*>(smem_raw + SM_MG);
    float* S = reinterpret_cast<float*>(smem_raw + SM_S);

    const int tid = threadIdx.x;
    const int bblk = blockIdx.x * TB;

    // phase-2 decomposition: tid = bhalf*256 + j*8 + ch  (bhalf uniform per warp)
    const int bhalf = tid >> 8;        // 0,1 -> batch pairs 0..3 / 4..7
    const int jj    = (tid >> 3) & 31; // row j
    const int ch    = tid & 7;         // owns columns c = ch + 8*s, s=0..3

    for (int mode = 0; mode < MM; ++mode) {
        // ---- phase 1: Gaussian weights as batch pairs ----
        {
            const int d = tid >> 1;
            const int half = tid & 1;
            const float li  = __ldg(&location[d * MM + mode]);
            const float lsi = __ldg(&log_scale[d * MM + mode]);
            const float inv = __expf(-lsi);
            const float cb = -0.5f * LOG_2PI_F - lsi;
            float pv[8];
            #pragma unroll
            for (int r = 0; r < 8; ++r) {
                const int bg = bblk + half * 8 + r;
                const float v = __ldg(&value[bg * MM + mode]);
                const float z = (v - li) * inv;
                pv[r] = __expf(fmaf(-0.5f * z, z, cb));
            }
            #pragma unroll
            for (int q = 0; q < 4; ++q)
                PP[d * 8 + half * 4 + q] = pack2(pv[2 * q], pv[2 * q + 1]);
        }
        __syncthreads();

        // ---- phase 2: margins, batch-pair packed ----
        // acc[s*4+q] = pair over b=(2bp,2bp+1), bp=bhalf*4+q, at (jj, c=ch+8s)
        {
            const float4* __restrict__ cptr =
                reinterpret_cast<const float4*>(g_spc) +
                (size_t)mode * (DD * RR * RR / 4) + jj * 8 + ch;   // per-d stride 256

            unsigned long long acc[16];
            #pragma unroll
            for (int k = 0; k < 16; ++k) acc[k] = 0ull;

            float4 cur[4], nxt[4];
            #pragma unroll
            for (int k = 0; k < 4; ++k) cur[k] = __ldg(cptr + k * 256);

            for (int d0 = 0; d0 < DD; d0 += 4) {
                if (d0 + 4 < DD) {
                    #pragma unroll
                    for (int k = 0; k < 4; ++k)
                        nxt[k] = __ldg(cptr + (size_t)(d0 + 4 + k) * 256);
                }
                #pragma unroll
                for (int k = 0; k < 4; ++k) {
                    const int d = d0 + k;
                    const ulonglong2* pr = reinterpret_cast<const ulonglong2*>(
                        PP + d * 8 + bhalf * 4);
                    const ulonglong2 pa = pr[0];  // q=0,1
                    const ulonglong2 pb = pr[1];  // q=2,3
                    const unsigned long long cs0 = splat2(cur[k].x);
                    const unsigned long long cs1 = splat2(cur[k].y);
                    const unsigned long long cs2 = splat2(cur[k].z);
                    const unsigned long long cs3 = splat2(cur[k].w);
                    fma2(acc[0],  pa.x, cs0); fma2(acc[1],  pa.y, cs0);
                    fma2(acc[2],  pb.x, cs0); fma2(acc[3],  pb.y, cs0);
                    fma2(acc[4],  pa.x, cs1); fma2(acc[5],  pa.y, cs1);
                    fma2(acc[6],  pb.x, cs1); fma2(acc[7],  pb.y, cs1);
                    fma2(acc[8],  pa.x, cs2); fma2(acc[9],  pa.y, cs2);
                    fma2(acc[10], pb.x, cs2); fma2(acc[11], pb.y, cs2);
                    fma2(acc[12], pa.x, cs3); fma2(acc[13], pa.y, cs3);
                    fma2(acc[14], pb.x, cs3); fma2(acc[15], pb.y, cs3);
                }
                #pragma unroll
                for (int k = 0; k < 4; ++k) cur[k] = nxt[k];
            }

            #pragma unroll
            for (int s = 0; s < 4; ++s)
                #pragma unroll
                for (int q = 0; q < 4; ++q)
                    MG[(bhalf * 4 + q) * (RR * RR) + jj * RR + ch + 8 * s] =
                        acc[s * 4 + q];
        }
        __syncthreads();

        // ---- phase 3: chain  prob <- prob @ margin  (S transposed) ----
        {
            const int bb = tid >> 5;       // batch within block (warp)
            const int lane = tid & 31;     // output column c
            const int bp = bb >> 1;
            const int parity = bb & 1;

            if (mode == 0) {
                float col[RR];
                #pragma unroll
                for (int r = 0; r < RR; ++r) {
                    float lo, hi;
                    unpack2(MG[bp * (RR * RR) + r * RR + lane], lo, hi);
                    col[r] = parity ? hi : lo;
                }
                float4* dst = reinterpret_cast<float4*>(
                    S + bb * (RR * S_STRIDE) + lane * S_STRIDE);
                #pragma unroll
                for (int k = 0; k < 8; ++k)
                    dst[k] = make_float4(col[4 * k], col[4 * k + 1],
                                         col[4 * k + 2], col[4 * k + 3]);
            } else {
                float m[RR];
                #pragma unroll
                for (int j = 0; j < RR; ++j) {
                    float lo, hi;
                    unpack2(MG[bp * (RR * RR) + j * RR + lane], lo, hi);
                    m[j] = parity ? hi : lo;
                }

                unsigned long long acc2[16];
                #pragma unroll
                for (int k = 0; k < 16; ++k) acc2[k] = 0ull;

                #pragma unroll
                for (int j = 0; j < RR; ++j) {
                    const unsigned long long mm = splat2(m[j]);
                    const ulonglong2* srow = reinterpret_cast<const ulonglong2*>(
                        S + bb * (RR * S_STRIDE) + j * S_STRIDE);
                    #pragma unroll
                    for (int k = 0; k < 8; ++k) {
                        ulonglong2 sv = srow[k];
                        fma2(acc2[2 * k], sv.x, mm);
                        fma2(acc2[2 * k + 1], sv.y, mm);
                    }
                }
                __syncthreads();  // all S reads complete before overwrite
                ulonglong2* dst = reinterpret_cast<ulonglong2*>(
                    S + bb * (RR * S_STRIDE) + lane * S_STRIDE);
                #pragma unroll
                for (int k = 0; k < 8; ++k) {
                    ulonglong2 v;
                    v.x = acc2[2 * k];
                    v.y = acc2[2 * k + 1];
                    dst[k] = v;
                }
            }
        }
        __syncthreads();
    }

    // ---- epilogue: trace + log ----
    {
        const int bb = tid >> 5;
        const int lane = tid & 31;
        float dv = S[bb * (RR * S_STRIDE) + lane * S_STRIDE + lane];
        #pragma unroll
        for (int o = 16; o > 0; o >>= 1) dv += __shfl_xor_sync(0xffffffffu, dv, o);
        if (lane == 0) {
            out[bblk + bb] = logf(fmaxf(dv, 1e-12f)) - g_lognorm;
        }
    }
}

extern "C" void kernel_launch(void* const* d_in, const int* in_sizes, int n_in,
                              void* d_out, int out_size) {
    const float* value     = (const float*)d_in[0];  // (B, M)
    const float* location  = (const float*)d_in[1];  // (D, M)
    const float* log_scale = (const float*)d_in[2];  // (D, M)
    const float* cores     = (const float*)d_in[3];  // (M, D, R, R)
    float* out = (float*)d_out;

    const int B = in_sizes[0] / MM;
    const int total_core = MM * DD * RR * RR;  // 2,097,152

    k_softplus<<<total_core / 1024, 1024>>>(cores);
    k_modesum<<<MM, 1024>>>();
    k_normchain<<<1, 1024>>>();

    cudaFuncSetAttribute(k_trip_main,
                         cudaFuncAttributeMaxDynamicSharedMemorySize, SMEM_TOTAL);
    k_trip_main<<<B / TB, NTHREADS, SMEM_TOTAL>>>(value, location, log_scale, out);
}

// round 6
// speedup vs baseline: 1.6962x; 1.0021x over previous
#include <cuda_runtime.h>
#include <cuda_bf16.h>

// Problem constants (TRIP log_prob): B=32768, M=8, D=256, R=32
#define MM 8
#define DD 256
#define RR 32
#define TB 16          // batch elements per block
#define NTHREADS 512   // 16 warps

#define LOG_2PI_F 1.8378770664093453f

// Scratch: permuted softplus(cores), per-mode core sums, log(trace(norm))
// Permuted layout: g_spc[mode][d][j][ch][s] where original c = ch + 8*s
// (ch in 0..7, s in 0..3). Permutation is within each 32-float row.
__device__ float g_spc[MM * DD * RR * RR];   // 8 MB
__device__ float g_s[MM * RR * RR];          // 32 KB (natural layout)
__device__ float g_lognorm;

// ---------------- f32x2 packed helpers (sm_100+) ----------------
__device__ __forceinline__ unsigned long long splat2(float x) {
    unsigned long long r;
    asm("mov.b64 %0, {%1, %1};" : "=l"(r) : "f"(x));
    return r;
}
__device__ __forceinline__ unsigned long long pack2(float lo, float hi) {
    unsigned long long r;
    asm("mov.b64 %0, {%1, %2};" : "=l"(r) : "f"(lo), "f"(hi));
    return r;
}
__device__ __forceinline__ void unpack2(unsigned long long v, float& lo, float& hi) {
    asm("mov.b64 {%0, %1}, %2;" : "=f"(lo), "=f"(hi) : "l"(v));
}
__device__ __forceinline__ void fma2(unsigned long long& acc,
                                     unsigned long long a,
                                     unsigned long long b) {
    asm("fma.rn.f32x2 %0, %1, %2, %0;" : "+l"(acc) : "l"(a), "l"(b));
}

// ---------------- kernel 0: softplus(cores) with column permutation ----------------
__global__ void k_softplus(const float* __restrict__ cores) {
    int i = blockIdx.x * blockDim.x + threadIdx.x;  // 2,097,152 threads
    float x = cores[i];
    float sp = (x > 20.0f) ? x : log1pf(expf(x));
    int c = i & 31;
    int ch = c & 7;
    int s = c >> 3;
    int row = i >> 5;                       // (mode,d,j) flat
    g_spc[(row << 5) + ch * 4 + s] = sp;    // permuted within row
}

// ---------------- kernel 1: per-mode core sums (un-permute into natural) ----------------
__global__ void k_modesum() {  // grid = MM blocks, 1024 threads
    int i = blockIdx.x;
    int t = threadIdx.x;  // permuted (j, pos) flat: pos = ch*4+s
    float a = 0.0f;
    const float* base = g_spc + (size_t)i * DD * RR * RR + t;
    #pragma unroll 4
    for (int d = 0; d < DD; ++d) a += base[d * (RR * RR)];
    int pos = t & 31;
    int j = t >> 5;
    int ch = pos >> 2;
    int s = pos & 3;
    int c = ch + 8 * s;                     // natural column
    g_s[i * RR * RR + j * RR + c] = a;
}

// ---------------- kernel 2: norm chain + log(trace) ----------------
__global__ void k_normchain() {  // 1 block, 1024 threads
    __shared__ float nrm[RR * RR];
    __shared__ float s[RR * RR];
    __shared__ float tmp[RR * RR];
    int t = threadIdx.x;
    int r = t >> 5, c = t & 31;
    nrm[t] = g_s[t];
    __syncthreads();
    for (int i = 1; i < MM; ++i) {
        s[t] = g_s[i * RR * RR + t];
        __syncthreads();
        float a = 0.0f;
        #pragma unroll
        for (int j = 0; j < RR; ++j) a += nrm[r * RR + j] * s[j * RR + c];
        tmp[t] = a;
        __syncthreads();
        nrm[t] = tmp[t];
        __syncthreads();
    }
    if (t == 0) {
        float tr = 0.0f;
        #pragma unroll
        for (int k = 0; k < RR; ++k) tr += nrm[k * (RR + 1)];
        g_lognorm = logf(tr);
    }
}

// ---------------- main fused kernel ----------------
// Dynamic smem layout:
//   PP : ulonglong [DD][8]   p batch-pairs (p_2bp, p_2bp+1), NOT splatted  16384 B
//   MG : ulonglong [8][RR*RR] margin batch-pairs: MG[bp][j*32+c]           65536 B
//   S  : float [TB][RR][36]  state transposed: S[b][c][r] = prob[r][c]     73728 B
#define SM_PP   0
#define SM_MG   16384
#define SM_S    (16384 + 65536)
#define SMEM_TOTAL (16384 + 65536 + 73728)
#define S_STRIDE 36

__global__ void __launch_bounds__(NTHREADS, 1)
k_trip_main(const float* __restrict__ value,
            const float* __restrict__ location,
            const float* __restrict__ log_scale,
            float* __restrict__ out) {
    extern __shared__ unsigned char smem_raw[];
    unsigned long long* PP = reinterpret_cast<unsigned long long*>(smem_raw + SM_PP);
    unsigned long long* MG = reinterpret_cast<unsigned long long*>(smem_raw + SM_MG);
    float* S = reinterpret_cast<float*>(smem_raw + SM_S);

    const int tid = threadIdx.x;
    const int bblk = blockIdx.x * TB;

    // phase-2 decomposition: tid = bhalf*256 + j*8 + ch  (bhalf uniform per warp)
    const int bhalf = tid >> 8;        // 0,1 -> batch pairs 0..3 / 4..7
    const int jj    = (tid >> 3) & 31; // row j
    const int ch    = tid & 7;         // owns columns c = ch + 8*s, s=0..3

    for (int mode = 0; mode < MM; ++mode) {
        // ---- phase 1: Gaussian weights as batch pairs ----
        {
            const int d = tid >> 1;
            const int half = tid & 1;
            const float li  = __ldg(&location[d * MM + mode]);
            const float lsi = __ldg(&log_scale[d * MM + mode]);
            const float inv = __expf(-lsi);
            const float cb = -0.5f * LOG_2PI_F - lsi;
            float pv[8];
            #pragma unroll
            for (int r = 0; r < 8; ++r) {
                const int bg = bblk + half * 8 + r;
                const float v = __ldg(&value[bg * MM + mode]);
                const float z = (v - li) * inv;
                pv[r] = __expf(fmaf(-0.5f * z, z, cb));
            }
            #pragma unroll
            for (int q = 0; q < 4; ++q)
                PP[d * 8 + half * 4 + q] = pack2(pv[2 * q], pv[2 * q + 1]);
        }
        __syncthreads();

        // ---- phase 2: margins, batch-pair packed ----
        // acc[s*4+q] = pair over b=(2bp,2bp+1), bp=bhalf*4+q, at (jj, c=ch+8s)
        {
            const float4* __restrict__ cptr =
                reinterpret_cast<const float4*>(g_spc) +
                (size_t)mode * (DD * RR * RR / 4) + jj * 8 + ch;   // per-d stride 256

            unsigned long long acc[16];
            #pragma unroll
            for (int k = 0; k < 16; ++k) acc[k] = 0ull;

            float4 cur[4], nxt[4];
            #pragma unroll
            for (int k = 0; k < 4; ++k) cur[k] = __ldg(cptr + k * 256);

            for (int d0 = 0; d0 < DD; d0 += 4) {
                if (d0 + 4 < DD) {
                    #pragma unroll
                    for (int k = 0; k < 4; ++k)
                        nxt[k] = __ldg(cptr + (size_t)(d0 + 4 + k) * 256);
                }
                #pragma unroll
                for (int k = 0; k < 4; ++k) {
                    const int d = d0 + k;
                    const ulonglong2* pr = reinterpret_cast<const ulonglong2*>(
                        PP + d * 8 + bhalf * 4);
                    const ulonglong2 pa = pr[0];  // q=0,1
                    const ulonglong2 pb = pr[1];  // q=2,3
                    const unsigned long long cs0 = splat2(cur[k].x);
                    const unsigned long long cs1 = splat2(cur[k].y);
                    const unsigned long long cs2 = splat2(cur[k].z);
                    const unsigned long long cs3 = splat2(cur[k].w);
                    fma2(acc[0],  pa.x, cs0); fma2(acc[1],  pa.y, cs0);
                    fma2(acc[2],  pb.x, cs0); fma2(acc[3],  pb.y, cs0);
                    fma2(acc[4],  pa.x, cs1); fma2(acc[5],  pa.y, cs1);
                    fma2(acc[6],  pb.x, cs1); fma2(acc[7],  pb.y, cs1);
                    fma2(acc[8],  pa.x, cs2); fma2(acc[9],  pa.y, cs2);
                    fma2(acc[10], pb.x, cs2); fma2(acc[11], pb.y, cs2);
                    fma2(acc[12], pa.x, cs3); fma2(acc[13], pa.y, cs3);
                    fma2(acc[14], pb.x, cs3); fma2(acc[15], pb.y, cs3);
                }
                #pragma unroll
                for (int k = 0; k < 4; ++k) cur[k] = nxt[k];
            }

            #pragma unroll
            for (int s = 0; s < 4; ++s)
                #pragma unroll
                for (int q = 0; q < 4; ++q)
                    MG[(bhalf * 4 + q) * (RR * RR) + jj * RR + ch + 8 * s] =
                        acc[s * 4 + q];
        }
        __syncthreads();

        // ---- phase 3: chain  prob <- prob @ margin  (S transposed) ----
        {
            const int bb = tid >> 5;       // batch within block (warp)
            const int lane = tid & 31;     // output column c
            const int bp = bb >> 1;
            const int parity = bb & 1;

            if (mode == 0) {
                float col[RR];
                #pragma unroll
                for (int r = 0; r < RR; ++r) {
                    float lo, hi;
                    unpack2(MG[bp * (RR * RR) + r * RR + lane], lo, hi);
                    col[r] = parity ? hi : lo;
                }
                float4* dst = reinterpret_cast<float4*>(
                    S + bb * (RR * S_STRIDE) + lane * S_STRIDE);
                #pragma unroll
                for (int k = 0; k < 8; ++k)
                    dst[k] = make_float4(col[4 * k], col[4 * k + 1],
                                         col[4 * k + 2], col[4 * k + 3]);
            } else {
                float m[RR];
                #pragma unroll
                for (int j = 0; j < RR; ++j) {
                    float lo, hi;
                    unpack2(MG[bp * (RR * RR) + j * RR + lane], lo, hi);
                    m[j] = parity ? hi : lo;
                }

                unsigned long long acc2[16];
                #pragma unroll
                for (int k = 0; k < 16; ++k) acc2[k] = 0ull;

                #pragma unroll
                for (int j = 0; j < RR; ++j) {
                    const unsigned long long mm = splat2(m[j]);
                    const ulonglong2* srow = reinterpret_cast<const ulonglong2*>(
                        S + bb * (RR * S_STRIDE) + j * S_STRIDE);
                    #pragma unroll
                    for (int k = 0; k < 8; ++k) {
                        ulonglong2 sv = srow[k];
                        fma2(acc2[2 * k], sv.x, mm);
                        fma2(acc2[2 * k + 1], sv.y, mm);
                    }
                }
                __syncthreads();  // all S reads complete before overwrite
                ulonglong2* dst = reinterpret_cast<ulonglong2*>(
                    S + bb * (RR * S_STRIDE) + lane * S_STRIDE);
                #pragma unroll
                for (int k = 0; k < 8; ++k) {
                    ulonglong2 v;
                    v.x = acc2[2 * k];
                    v.y = acc2[2 * k + 1];
                    dst[k] = v;
                }
            }
        }
        __syncthreads();
    }

    // ---- epilogue: trace + log ----
    {
        const int bb = tid >> 5;
        const int lane = tid & 31;
        float dv = S[bb * (RR * S_STRIDE) + lane * S_STRIDE + lane];
        #pragma unroll
        for (int o = 16; o > 0; o >>= 1) dv += __shfl_xor_sync(0xffffffffu, dv, o);
        if (lane == 0) {
            out[bblk + bb] = logf(fmaxf(dv, 1e-12f)) - g_lognorm;
        }
    }
}

extern "C" void kernel_launch(void* const* d_in, const int* in_sizes, int n_in,
                              void* d_out, int out_size) {
    const float* value     = (const float*)d_in[0];  // (B, M)
    const float* location  = (const float*)d_in[1];  // (D, M)
    const float* log_scale = (const float*)d_in[2];  // (D, M)
    const float* cores     = (const float*)d_in[3];  // (M, D, R, R)
    float* out = (float*)d_out;

    const int B = in_sizes[0] / MM;
    const int total_core = MM * DD * RR * RR;  // 2,097,152

    k_softplus<<<total_core / 1024, 1024>>>(cores);
    k_modesum<<<MM, 1024>>>();
    k_normchain<<<1, 1024>>>();

    cudaFuncSetAttribute(k_trip_main,
                         cudaFuncAttributeMaxDynamicSharedMemorySize, SMEM_TOTAL);
    k_trip_main<<<B / TB, NTHREADS, SMEM_TOTAL>>>(value, location, log_scale, out);
}

// round 8
// speedup vs baseline: 4.1739x; 2.4607x over previous
#include <cuda_runtime.h>
#include <cuda_bf16.h>
#include <cstdint>

// Problem constants (TRIP log_prob): B=32768, M=8, D=256, R=32
#define MM 8
#define DD 256
#define RR 32
#define NN (RR * RR)          // 1024
#define MT 128                // batch rows per margin block
#define NG 128                // N per group
#define NGROUPS (NN / NG)     // 8
#define TBC 16                // batches per chain block
#define BTOT 32768

#define LOG_2PI_F 1.8378770664093453f

// ---------------- global scratch ----------------
__device__ __nv_bfloat16 g_cb[MM * NN * DD];              // 4 MB: C^T bf16 [mode][n][d], n=32j+c
__device__ __nv_bfloat16 g_marg[(size_t)BTOT * MM * NN];  // 512 MB: margins bf16 [b][mode][n]
__device__ float g_s[MM * NN];                            // per-mode core sums (natural)
__device__ float g_lognorm;

// ---------------- f32x2 packed helpers (sm_100) ----------------
__device__ __forceinline__ unsigned long long splat2(float x) {
    unsigned long long r;
    asm("mov.b64 %0, {%1, %1};" : "=l"(r) : "f"(x));
    return r;
}
__device__ __forceinline__ void fma2(unsigned long long& acc,
                                     unsigned long long a,
                                     unsigned long long b) {
    asm("fma.rn.f32x2 %0, %1, %2, %0;" : "+l"(acc) : "l"(a), "l"(b));
}
__device__ __forceinline__ uint32_t bf2_bits(float a, float b) {
    __nv_bfloat162 h = __floats2bfloat162_rn(a, b);  // .x=a (low), .y=b (high)
    return *reinterpret_cast<uint32_t*>(&h);
}

// ---------------- warp MMA helpers (plain sm_100-legal PTX) ----------------
__device__ __forceinline__ uint32_t smem_u32(const void* p) {
    uint32_t a;
    asm("{ .reg .u64 t; cvta.to.shared.u64 t, %1; cvt.u32.u64 %0, t; }" : "=r"(a) : "l"(p));
    return a;
}
__device__ __forceinline__ void ldsm4(uint32_t& r0, uint32_t& r1,
                                      uint32_t& r2, uint32_t& r3, uint32_t addr) {
    asm volatile("ldmatrix.sync.aligned.m8n8.x4.shared.b16 {%0,%1,%2,%3}, [%4];"
                 : "=r"(r0), "=r"(r1), "=r"(r2), "=r"(r3) : "r"(addr));
}
__device__ __forceinline__ void mma_bf16(float* d, const uint32_t* a, const uint32_t* b) {
    asm volatile(
        "mma.sync.aligned.m16n8k16.row.col.f32.bf16.bf16.f32 "
        "{%0,%1,%2,%3}, {%4,%5,%6,%7}, {%8,%9}, {%0,%1,%2,%3};"
        : "+f"(d[0]), "+f"(d[1]), "+f"(d[2]), "+f"(d[3])
        : "r"(a[0]), "r"(a[1]), "r"(a[2]), "r"(a[3]), "r"(b[0]), "r"(b[1]));
}
__device__ __forceinline__ void cp_async16(uint32_t smem_addr, const void* gptr) {
    asm volatile("cp.async.cg.shared.global [%0], [%1], 16;"
                 :: "r"(smem_addr), "l"(gptr) : "memory");
}
__device__ __forceinline__ void cp_commit() {
    asm volatile("cp.async.commit_group;" ::: "memory");
}
template <int N>
__device__ __forceinline__ void cp_wait() {
    asm volatile("cp.async.wait_group %0;" :: "n"(N) : "memory");
}

// swizzled smem address: rows of 512B (256 bf16), 16B chunk XOR (row&7)
__device__ __forceinline__ uint32_t swz(uint32_t base, int row, int chunk) {
    return base + row * 512 + (((chunk) ^ (row & 7)) << 4);
}

// ---------------- kernel: prep  softplus(cores) -> g_cb (transposed bf16) ----------------
__global__ void k_prep(const float* __restrict__ cores) {
    int i = blockIdx.x * blockDim.x + threadIdx.x;  // 2,097,152
    float x = cores[i];
    float sp = (x > 20.0f) ? x : log1pf(expf(x));
    int c = i & 31;
    int j = (i >> 5) & 31;
    int d = (i >> 10) & 255;
    int mode = i >> 18;
    int n = j * 32 + c;
    g_cb[((size_t)mode * NN + n) * DD + d] = __float2bfloat16(sp);
}

// ---------------- kernel: per-mode core sums (from bf16 C^T) ----------------
__global__ void k_modesum() {  // grid = MM, 1024 threads
    int mode = blockIdx.x;
    int t = threadIdx.x;  // n = 32j + c
    const uint4* p = reinterpret_cast<const uint4*>(&g_cb[((size_t)mode * NN + t) * DD]);
    float a = 0.0f;
    #pragma unroll 8
    for (int k = 0; k < 32; ++k) {
        uint4 w = p[k];
        const __nv_bfloat162* h = reinterpret_cast<const __nv_bfloat162*>(&w);
        #pragma unroll
        for (int e = 0; e < 4; ++e) {
            float2 f = __bfloat1622float2(h[e]);
            a += f.x + f.y;
        }
    }
    g_s[mode * NN + t] = a;
}

// ---------------- kernel: norm chain + log(trace) ----------------
__global__ void k_normchain() {  // 1 block, 1024 threads
    __shared__ float nrm[NN];
    __shared__ float s[NN];
    __shared__ float tmp[NN];
    int t = threadIdx.x;
    int r = t >> 5, c = t & 31;
    nrm[t] = g_s[t];
    __syncthreads();
    for (int i = 1; i < MM; ++i) {
        s[t] = g_s[i * NN + t];
        __syncthreads();
        float a = 0.0f;
        #pragma unroll
        for (int j = 0; j < RR; ++j) a += nrm[r * RR + j] * s[j * RR + c];
        tmp[t] = a;
        __syncthreads();
        nrm[t] = tmp[t];
        __syncthreads();
    }
    if (t == 0) {
        float tr = 0.0f;
        #pragma unroll
        for (int k = 0; k < RR; ++k) tr += nrm[k * (RR + 1)];
        g_lognorm = logf(tr);
    }
}

// ---------------- kernel: margins via warp-level mma.sync ----------------
// grid = (B/128)*8, mode = bx>>8 (same-mode blocks adjacent -> L2 reuse of C^T).
// SMEM: A = E[128][256] bf16 swizzled (64KB) | W double buffer 2 x [128][256] (128KB)
#define SM_A 0
#define SM_W0 65536
#define SM_W1 (65536 + 65536)
#define M_SMEM (3 * 65536)

__global__ void __launch_bounds__(512, 1)
k_margins(const float* __restrict__ value,
          const float* __restrict__ location,
          const float* __restrict__ log_scale) {
    extern __shared__ unsigned char sm[];
    __shared__ float sloc[DD], sinv[DD], scb[DD];

    const uint32_t sb = smem_u32(sm);
    const uint32_t aA = sb + SM_A;
    const uint32_t aW[2] = {sb + SM_W0, sb + SM_W1};

    const int tid = threadIdx.x;
    const int wid = tid >> 5;
    const int lane = tid & 31;
    const int mode = blockIdx.x >> 8;
    const int btile = blockIdx.x & 255;
    const int bblk = btile * MT;

    // ---- prefetch W groups 0 and 1 (cp.async, 4096 x 16B each) ----
    const __nv_bfloat16* wsrc = &g_cb[(size_t)mode * NN * DD];
    {
        #pragma unroll
        for (int k = 0; k < 8; ++k) {
            int q = tid + k * 512;          // 0..4095
            int row = q >> 5;               // n row 0..127
            int ch = q & 31;                // 16B chunk
            cp_async16(swz(aW[0], row, ch), wsrc + (size_t)row * DD + ch * 8);
        }
        cp_commit();
        #pragma unroll
        for (int k = 0; k < 8; ++k) {
            int q = tid + k * 512;
            int row = q >> 5;
            int ch = q & 31;
            cp_async16(swz(aW[1], row, ch), wsrc + (size_t)(NG + row) * DD + ch * 8);
        }
        cp_commit();
    }

    // ---- params + E tile (Gaussian weights, bf16, swizzled A) ----
    if (tid < DD) {
        float lsi = __ldg(&log_scale[tid * MM + mode]);
        sloc[tid] = __ldg(&location[tid * MM + mode]);
        sinv[tid] = __expf(-lsi);
        scb[tid] = -0.5f * LOG_2PI_F - lsi;
    }
    __syncthreads();
    {
        const int b = tid >> 2;     // batch row 0..127
        const int quad = tid & 3;   // d-range quad*64..+63
        const float v = __ldg(&value[(size_t)(bblk + b) * MM + mode]);
        #pragma unroll
        for (int dd = 0; dd < 64; dd += 2) {
            const int d = quad * 64 + dd;
            float z0 = (v - sloc[d]) * sinv[d];
            float p0 = __expf(fmaf(-0.5f * z0, z0, scb[d]));
            float z1 = (v - sloc[d + 1]) * sinv[d + 1];
            float p1 = __expf(fmaf(-0.5f * z1, z1, scb[d + 1]));
            uint32_t addr = swz(aA, b, d >> 3) + (d & 7) * 2;
            asm volatile("st.shared.b32 [%0], %1;" :: "r"(addr), "r"(bf2_bits(p0, p1)));
        }
    }

    // ---- warp tiling: 4(m) x 4(n) warps, warp tile m32 x n32 ----
    const int mi = wid & 3;         // m-tile: rows mi*32..+31
    const int ni = wid >> 2;        // n-tile within group: cols ni*32..+31
    // A ldmatrix lane address components (bit3 -> row+8, bit4 -> chunk+1)
    const int a_row = mi * 32 + (lane & 7) + ((lane >> 3) & 1) * 8;
    const int a_cad = lane >> 4;
    // B ldmatrix lane address components (bit3 -> chunk+1, bit4 -> row+8)
    const int b_rowo = (lane & 7) + (lane >> 4) * 8;
    const int b_cad = (lane >> 3) & 1;

    for (int g = 0; g < NGROUPS; ++g) {
        cp_wait<1>();           // group g resident (for g>=6 both resident anyway)
        if (g >= NGROUPS - 2) { cp_wait<0>(); }
        __syncthreads();

        const uint32_t W = aW[g & 1];
        float acc[2][4][4];
        #pragma unroll
        for (int mt = 0; mt < 2; ++mt)
            #pragma unroll
            for (int nt = 0; nt < 4; ++nt)
                #pragma unroll
                for (int e = 0; e < 4; ++e) acc[mt][nt][e] = 0.0f;

        #pragma unroll 4
        for (int ks = 0; ks < 16; ++ks) {
            const int c0 = 2 * ks;
            uint32_t a[2][4];
            #pragma unroll
            for (int mt = 0; mt < 2; ++mt) {
                int row = a_row + mt * 16;
                ldsm4(a[mt][0], a[mt][1], a[mt][2], a[mt][3],
                      swz(aA, row, c0 + a_cad));
            }
            uint32_t b[4][2];
            #pragma unroll
            for (int pr = 0; pr < 2; ++pr) {
                int row = ni * 32 + pr * 16 + b_rowo;
                uint32_t q0, q1, q2, q3;
                ldsm4(q0, q1, q2, q3, swz(W, row, c0 + b_cad));
                b[pr * 2][0] = q0;     b[pr * 2][1] = q1;
                b[pr * 2 + 1][0] = q2; b[pr * 2 + 1][1] = q3;
            }
            #pragma unroll
            for (int mt = 0; mt < 2; ++mt)
                #pragma unroll
                for (int nt = 0; nt < 4; ++nt)
                    mma_bf16(acc[mt][nt], a[mt], b[nt]);
        }
        __syncthreads();  // all warps done reading W[g&1] before refill

        // prefetch group g+2 into the buffer just freed
        if (g + 2 < NGROUPS) {
            #pragma unroll
            for (int k = 0; k < 8; ++k) {
                int q = tid + k * 512;
                int row = q >> 5;
                int ch = q & 31;
                cp_async16(swz(aW[g & 1], row, ch),
                           wsrc + (size_t)((g + 2) * NG + row) * DD + ch * 8);
            }
            cp_commit();
        }

        // ---- store margins bf16 (fragment layout: row=l/4(+8), col=2(l%4)) ----
        #pragma unroll
        for (int mt = 0; mt < 2; ++mt) {
            const int row = bblk + mi * 32 + mt * 16 + (lane >> 2);
            #pragma unroll
            for (int nt = 0; nt < 4; ++nt) {
                const int col = g * NG + ni * 32 + nt * 8 + 2 * (lane & 3);
                uint32_t lo = bf2_bits(acc[mt][nt][0], acc[mt][nt][1]);
                uint32_t hi = bf2_bits(acc[mt][nt][2], acc[mt][nt][3]);
                *reinterpret_cast<uint32_t*>(
                    &g_marg[((size_t)row * MM + mode) * NN + col]) = lo;
                *reinterpret_cast<uint32_t*>(
                    &g_marg[((size_t)(row + 8) * MM + mode) * NN + col]) = hi;
            }
        }
    }
}

// ---------------- kernel: chain (FFMA2, margins from global bf16) ----------------
// SMEM: MG double buffer 2 x [16][1024] f32 (128 KB) | S [16][32][36] f32 (72 KB)
#define SMC_S (2 * 65536)
#define C_SMEM (2 * 65536 + 73728)
#define S_STRIDE 36

__global__ void __launch_bounds__(512, 1)
k_chain(float* __restrict__ out) {
    extern __shared__ unsigned char sm[];
    float* MG = reinterpret_cast<float*>(sm);
    float* S = reinterpret_cast<float*>(sm + SMC_S);

    const int tid = threadIdx.x;
    const int bb = tid >> 5;    // batch within block (warp)
    const int lane = tid & 31;
    const int bblk = blockIdx.x * TBC;

    // preload mode 0 margins: 16 x 1024 bf16 = 2048 uint4
    #pragma unroll
    for (int k = 0; k < 4; ++k) {
        int q = tid + k * 512;
        int row = q >> 7;
        int c8 = q & 127;
        uint4 w = *reinterpret_cast<const uint4*>(
            &g_marg[((size_t)(bblk + row) * MM + 0) * NN + c8 * 8]);
        const __nv_bfloat162* h = reinterpret_cast<const __nv_bfloat162*>(&w);
        float2 a = __bfloat1622float2(h[0]);
        float2 b = __bfloat1622float2(h[1]);
        float2 c = __bfloat1622float2(h[2]);
        float2 d = __bfloat1622float2(h[3]);
        float4* dst = reinterpret_cast<float4*>(&MG[row * NN + c8 * 8]);
        dst[0] = make_float4(a.x, a.y, b.x, b.y);
        dst[1] = make_float4(c.x, c.y, d.x, d.y);
    }
    __syncthreads();

    for (int m = 0; m < MM; ++m) {
        float* MGc = MG + (m & 1) * (TBC * NN);

        // prefetch next mode's margins into registers
        uint4 pf[4];
        if (m < MM - 1) {
            #pragma unroll
            for (int k = 0; k < 4; ++k) {
                int q = tid + k * 512;
                int row = q >> 7;
                int c8 = q & 127;
                pf[k] = *reinterpret_cast<const uint4*>(
                    &g_marg[((size_t)(bblk + row) * MM + (m + 1)) * NN + c8 * 8]);
            }
        }

        if (m == 0) {
            // initialize transposed state: S[bb][c][r] = margin[bb][r][c]
            float col[RR];
            #pragma unroll
            for (int r = 0; r < RR; ++r)
                col[r] = MGc[bb * NN + r * RR + lane];
            float4* dst = reinterpret_cast<float4*>(
                S + bb * (RR * S_STRIDE) + lane * S_STRIDE);
            #pragma unroll
            for (int k = 0; k < 8; ++k)
                dst[k] = make_float4(col[4 * k], col[4 * k + 1],
                                     col[4 * k + 2], col[4 * k + 3]);
        } else {
            float mj[RR];
            #pragma unroll
            for (int j = 0; j < RR; ++j)
                mj[j] = MGc[bb * NN + j * RR + lane];

            unsigned long long acc2[16];
            #pragma unroll
            for (int k = 0; k < 16; ++k) acc2[k] = 0ull;

            #pragma unroll
            for (int j = 0; j < RR; ++j) {
                const unsigned long long mmv = splat2(mj[j]);
                const ulonglong2* srow = reinterpret_cast<const ulonglong2*>(
                    S + bb * (RR * S_STRIDE) + j * S_STRIDE);
                #pragma unroll
                for (int k = 0; k < 8; ++k) {
                    ulonglong2 sv = srow[k];
                    fma2(acc2[2 * k], sv.x, mmv);
                    fma2(acc2[2 * k + 1], sv.y, mmv);
                }
            }
            __syncwarp();  // S is warp-private: all reads done before overwrite
            ulonglong2* dst = reinterpret_cast<ulonglong2*>(
                S + bb * (RR * S_STRIDE) + lane * S_STRIDE);
            #pragma unroll
            for (int k = 0; k < 8; ++k) {
                ulonglong2 v;
                v.x = acc2[2 * k];
                v.y = acc2[2 * k + 1];
                dst[k] = v;
            }
        }

        // stage prefetched margins into the other buffer
        if (m < MM - 1) {
            float* MGn = MG + ((m + 1) & 1) * (TBC * NN);
            #pragma unroll
            for (int k = 0; k < 4; ++k) {
                int q = tid + k * 512;
                int row = q >> 7;
                int c8 = q & 127;
                const __nv_bfloat162* h =
                    reinterpret_cast<const __nv_bfloat162*>(&pf[k]);
                float2 a = __bfloat1622float2(h[0]);
                float2 b = __bfloat1622float2(h[1]);
                float2 c = __bfloat1622float2(h[2]);
                float2 d = __bfloat1622float2(h[3]);
                float4* dst = reinterpret_cast<float4*>(&MGn[row * NN + c8 * 8]);
                dst[0] = make_float4(a.x, a.y, b.x, b.y);
                dst[1] = make_float4(c.x, c.y, d.x, d.y);
            }
        }
        __syncthreads();
    }

    // epilogue: trace + log
    {
        float dv = S[bb * (RR * S_STRIDE) + lane * S_STRIDE + lane];
        #pragma unroll
        for (int o = 16; o > 0; o >>= 1) dv += __shfl_xor_sync(0xffffffffu, dv, o);
        if (lane == 0)
            out[bblk + bb] = logf(fmaxf(dv, 1e-12f)) - g_lognorm;
    }
}

// ---------------- launch ----------------
extern "C" void kernel_launch(void* const* d_in, const int* in_sizes, int n_in,
                              void* d_out, int out_size) {
    const float* value     = (const float*)d_in[0];  // (B, M)
    const float* location  = (const float*)d_in[1];  // (D, M)
    const float* log_scale = (const float*)d_in[2];  // (D, M)
    const float* cores     = (const float*)d_in[3];  // (M, D, R, R)
    float* out = (float*)d_out;

    const int B = in_sizes[0] / MM;               // 32768
    const int total_core = MM * DD * RR * RR;     // 2,097,152

    k_prep<<<total_core / 512, 512>>>(cores);
    k_modesum<<<MM, 1024>>>();
    k_normchain<<<1, 1024>>>();

    static bool attr_done = false;
    if (!attr_done) {
        cudaFuncSetAttribute(k_margins,
                             cudaFuncAttributeMaxDynamicSharedMemorySize, M_SMEM);
        cudaFuncSetAttribute(k_chain,
                             cudaFuncAttributeMaxDynamicSharedMemorySize, C_SMEM);
        attr_done = true;
    }

    k_margins<<<(B / MT) * MM, 512, M_SMEM>>>(value, location, log_scale);
    k_chain<<<B / TBC, 512, C_SMEM>>>(out);
}

// round 9
// speedup vs baseline: 4.3608x; 1.0448x over previous
#include <cuda_runtime.h>
#include <cuda_bf16.h>
#include <cstdint>

// Problem constants (TRIP log_prob): B=32768, M=8, D=256, R=32
#define MM 8
#define DD 256
#define RR 32
#define NN (RR * RR)          // 1024
#define MT 128                // batch rows per margin block
#define NG 128                // N per group
#define NGROUPS (NN / NG)     // 8
#define BTOT 32768

#define LOG_2PI_F 1.8378770664093453f

// ---------------- global scratch ----------------
// B fragments pre-permuted for mma.sync m16n8k16:
// uint4 index u = ((((mode*4+ni)*8 + g)*16 + kstep)*2 + half)*32 + lane
// components: c32 = (ntile&1)*2 + isb1, bf16 slot = k parity; ntile = half*2 + (c32>>1)
__device__ uint4 g_bf4[MM * 4 * 8 * 16 * 2 * 32];         // 4 MB
__device__ __nv_bfloat16 g_marg[(size_t)BTOT * MM * NN];  // 512 MB margins [b][mode][n]
__device__ float g_s[MM * NN];                            // per-mode core sums (f32)
__device__ float g_lognorm;

// ---------------- helpers ----------------
__device__ __forceinline__ float softplus_f(float x) {
    return (x > 20.0f) ? x : log1pf(expf(x));
}
__device__ __forceinline__ unsigned long long splat2(float x) {
    unsigned long long r;
    asm("mov.b64 %0, {%1, %1};" : "=l"(r) : "f"(x));
    return r;
}
__device__ __forceinline__ void fma2(unsigned long long& acc,
                                     unsigned long long a,
                                     unsigned long long b) {
    asm("fma.rn.f32x2 %0, %1, %2, %0;" : "+l"(acc) : "l"(a), "l"(b));
}
__device__ __forceinline__ void unpack2(unsigned long long v, float& lo, float& hi) {
    asm("mov.b64 {%0, %1}, %2;" : "=f"(lo), "=f"(hi) : "l"(v));
}
__device__ __forceinline__ uint32_t bf2_bits(float a, float b) {
    __nv_bfloat162 h = __floats2bfloat162_rn(a, b);  // .x=a (low), .y=b (high)
    return *reinterpret_cast<uint32_t*>(&h);
}
__device__ __forceinline__ uint32_t smem_u32(const void* p) {
    uint32_t a;
    asm("{ .reg .u64 t; cvta.to.shared.u64 t, %1; cvt.u32.u64 %0, t; }" : "=r"(a) : "l"(p));
    return a;
}
__device__ __forceinline__ void ldsm4(uint32_t& r0, uint32_t& r1,
                                      uint32_t& r2, uint32_t& r3, uint32_t addr) {
    asm volatile("ldmatrix.sync.aligned.m8n8.x4.shared.b16 {%0,%1,%2,%3}, [%4];"
                 : "=r"(r0), "=r"(r1), "=r"(r2), "=r"(r3) : "r"(addr));
}
__device__ __forceinline__ void mma_bf16(float* d, const uint32_t* a,
                                         uint32_t b0, uint32_t b1) {
    asm volatile(
        "mma.sync.aligned.m16n8k16.row.col.f32.bf16.bf16.f32 "
        "{%0,%1,%2,%3}, {%4,%5,%6,%7}, {%8,%9}, {%0,%1,%2,%3};"
        : "+f"(d[0]), "+f"(d[1]), "+f"(d[2]), "+f"(d[3])
        : "r"(a[0]), "r"(a[1]), "r"(a[2]), "r"(a[3]), "r"(b0), "r"(b1));
}
// swizzled smem address: rows of 512B (256 bf16), 16B chunk XOR (row&7)
__device__ __forceinline__ uint32_t swz(uint32_t base, int row, int chunk) {
    return base + row * 512 + (((chunk) ^ (row & 7)) << 4);
}

// ---------------- kernel: prep  softplus(cores) -> B fragments ----------------
// One thread per output uint4: gathers 8 core elements, softplus, packs bf16.
__global__ void k_prep(const float* __restrict__ cores) {
    int u = blockIdx.x * blockDim.x + threadIdx.x;  // 262144
    int lane = u & 31;
    int half = (u >> 5) & 1;
    int ks = (u >> 6) & 15;
    int g = (u >> 10) & 7;
    int ni = (u >> 13) & 3;
    int mode = u >> 15;
    int ncol = lane >> 2, tig = lane & 3;

    uint4 out;
    uint32_t comp[4];
    #pragma unroll
    for (int c32 = 0; c32 < 4; ++c32) {
        int ntile = half * 2 + (c32 >> 1);
        int isb1 = c32 & 1;
        int n = g * 128 + ni * 32 + ntile * 8 + ncol;
        int d = ks * 16 + isb1 * 8 + tig * 2;
        size_t base = (size_t)mode * (DD * NN) + (size_t)d * NN + n;
        float x0 = __ldg(&cores[base]);
        float x1 = __ldg(&cores[base + NN]);   // d+1
        comp[c32] = bf2_bits(softplus_f(x0), softplus_f(x1));
    }
    out.x = comp[0]; out.y = comp[1]; out.z = comp[2]; out.w = comp[3];
    g_bf4[u] = out;
}

// ---------------- kernel: per-mode core sums (f32, straight from cores) ----------------
__global__ void k_modesum(const float* __restrict__ cores) {  // grid = MM, 1024 thr
    int mode = blockIdx.x;
    int t = threadIdx.x;  // n = 32j + c
    float a = 0.0f;
    const float* base = cores + (size_t)mode * (DD * NN) + t;
    #pragma unroll 4
    for (int d = 0; d < DD; ++d) a += softplus_f(base[(size_t)d * NN]);
    g_s[mode * NN + t] = a;
}

// ---------------- kernel: norm chain + log(trace) ----------------
__global__ void k_normchain() {  // 1 block, 1024 threads
    __shared__ float nrm[NN];
    __shared__ float s[NN];
    __shared__ float tmp[NN];
    int t = threadIdx.x;
    int r = t >> 5, c = t & 31;
    nrm[t] = g_s[t];
    __syncthreads();
    for (int i = 1; i < MM; ++i) {
        s[t] = g_s[i * NN + t];
        __syncthreads();
        float a = 0.0f;
        #pragma unroll
        for (int j = 0; j < RR; ++j) a += nrm[r * RR + j] * s[j * RR + c];
        tmp[t] = a;
        __syncthreads();
        nrm[t] = tmp[t];
        __syncthreads();
    }
    if (t == 0) {
        float tr = 0.0f;
        #pragma unroll
        for (int k = 0; k < RR; ++k) tr += nrm[k * (RR + 1)];
        g_lognorm = logf(tr);
    }
}

// ---------------- kernel: margins (HMMA; A via smem+ldsm, B via global frags) ----------------
// grid = (B/128)*8, mode = bx>>8. SMEM: A = E[128][256] bf16 swizzled (64KB) only.
#define M_SMEM 65536

__global__ void __launch_bounds__(512, 1)
k_margins(const float* __restrict__ value,
          const float* __restrict__ location,
          const float* __restrict__ log_scale) {
    extern __shared__ unsigned char sm[];
    __shared__ float sloc[DD], sinv[DD], scb[DD];

    const uint32_t aA = smem_u32(sm);
    const int tid = threadIdx.x;
    const int wid = tid >> 5;
    const int lane = tid & 31;
    const int mode = blockIdx.x >> 8;
    const int bblk = (blockIdx.x & 255) * MT;

    if (tid < DD) {
        float lsi = __ldg(&log_scale[tid * MM + mode]);
        sloc[tid] = __ldg(&location[tid * MM + mode]);
        sinv[tid] = __expf(-lsi);
        scb[tid] = -0.5f * LOG_2PI_F - lsi;
    }
    __syncthreads();

    // ---- E tile: Gaussian weights bf16 into swizzled A smem ----
    {
        const int b = tid >> 2;     // batch row 0..127
        const int quad = tid & 3;   // d-range quad*64..+63
        const float v = __ldg(&value[(size_t)(bblk + b) * MM + mode]);
        #pragma unroll
        for (int dd = 0; dd < 64; dd += 2) {
            const int d = quad * 64 + dd;
            float z0 = (v - sloc[d]) * sinv[d];
            float p0 = __expf(fmaf(-0.5f * z0, z0, scb[d]));
            float z1 = (v - sloc[d + 1]) * sinv[d + 1];
            float p1 = __expf(fmaf(-0.5f * z1, z1, scb[d + 1]));
            uint32_t addr = swz(aA, b, d >> 3) + (d & 7) * 2;
            asm volatile("st.shared.b32 [%0], %1;" :: "r"(addr), "r"(bf2_bits(p0, p1)));
        }
    }
    __syncthreads();

    // ---- warp tiling: 4(m) x 4(n), warp tile m32 x n32 ----
    const int mi = wid & 3;
    const int ni = wid >> 2;
    const int a_row = mi * 32 + (lane & 7) + ((lane >> 3) & 1) * 8;
    const int a_cad = lane >> 4;

    const uint4* __restrict__ bbase =
        g_bf4 + (size_t)((mode * 4 + ni) * 8192) + lane;  // + idx*64 (+32 for half 1)

    // distance-2 prefetch pipeline over the 128 (g,ks) steps
    uint4 P0 = __ldg(bbase + 0),  P1 = __ldg(bbase + 32);
    uint4 Q0 = __ldg(bbase + 64), Q1 = __ldg(bbase + 96);

    for (int g = 0; g < NGROUPS; ++g) {
        float acc[2][4][4];
        #pragma unroll
        for (int mt = 0; mt < 2; ++mt)
            #pragma unroll
            for (int nt = 0; nt < 4; ++nt)
                #pragma unroll
                for (int e = 0; e < 4; ++e) acc[mt][nt][e] = 0.0f;

        #pragma unroll
        for (int ks = 0; ks < 16; ++ks) {
            int nx = g * 16 + ks + 2;
            nx = (nx > 127) ? 127 : nx;
            uint4 R0 = __ldg(bbase + nx * 64);
            uint4 R1 = __ldg(bbase + nx * 64 + 32);

            uint32_t a0[4], a1[4];
            ldsm4(a0[0], a0[1], a0[2], a0[3], swz(aA, a_row, 2 * ks + a_cad));
            ldsm4(a1[0], a1[1], a1[2], a1[3], swz(aA, a_row + 16, 2 * ks + a_cad));

            mma_bf16(acc[0][0], a0, P0.x, P0.y);
            mma_bf16(acc[0][1], a0, P0.z, P0.w);
            mma_bf16(acc[0][2], a0, P1.x, P1.y);
            mma_bf16(acc[0][3], a0, P1.z, P1.w);
            mma_bf16(acc[1][0], a1, P0.x, P0.y);
            mma_bf16(acc[1][1], a1, P0.z, P0.w);
            mma_bf16(acc[1][2], a1, P1.x, P1.y);
            mma_bf16(acc[1][3], a1, P1.z, P1.w);

            P0 = Q0; P1 = Q1; Q0 = R0; Q1 = R1;
        }

        // ---- store margins bf16 (fragment layout: row=l/4(+8), col=2(l%4)) ----
        #pragma unroll
        for (int mt = 0; mt < 2; ++mt) {
            const int row = bblk + mi * 32 + mt * 16 + (lane >> 2);
            #pragma unroll
            for (int nt = 0; nt < 4; ++nt) {
                const int col = g * NG + ni * 32 + nt * 8 + 2 * (lane & 3);
                uint32_t lo = bf2_bits(acc[mt][nt][0], acc[mt][nt][1]);
                uint32_t hi = bf2_bits(acc[mt][nt][2], acc[mt][nt][3]);
                *reinterpret_cast<uint32_t*>(
                    &g_marg[((size_t)row * MM + mode) * NN + col]) = lo;
                *reinterpret_cast<uint32_t*>(
                    &g_marg[((size_t)(row + 8) * MM + mode) * NN + col]) = hi;
            }
        }
    }
}

// ---------------- kernel: chain (state rows in registers, M rows broadcast) ----------------
// 256 thr / 8 warps / 8 batch per block, occupancy 2. Per-warp smem staging,
// row stride 40 f32 (160B) to break store bank conflicts; inner reads are broadcast.
#define CH_STR 40
#define C_SMEM (8 * 32 * CH_STR * 4)   // 40960 B

__global__ void __launch_bounds__(256, 2)
k_chain(float* __restrict__ out) {
    extern __shared__ float Mst_all[];
    const int tid = threadIdx.x;
    const int wid = tid >> 5;
    const int lane = tid & 31;
    const int b = blockIdx.x * 8 + wid;

    float* Mst = Mst_all + wid * (32 * CH_STR);
    const uint4* __restrict__ gsrc =
        reinterpret_cast<const uint4*>(g_marg) + (size_t)b * MM * 128;

    // stage helper pattern: lane l owns M row l (32 bf16 = 4 uint4 contiguous)
    uint4 w[4];
    #pragma unroll
    for (int k = 0; k < 4; ++k) w[k] = __ldg(gsrc + lane * 4 + k);
    #pragma unroll
    for (int k = 0; k < 4; ++k) {
        const __nv_bfloat162* h = reinterpret_cast<const __nv_bfloat162*>(&w[k]);
        float2 f0 = __bfloat1622float2(h[0]);
        float2 f1 = __bfloat1622float2(h[1]);
        float2 f2 = __bfloat1622float2(h[2]);
        float2 f3 = __bfloat1622float2(h[3]);
        float4* dst = reinterpret_cast<float4*>(&Mst[lane * CH_STR + k * 8]);
        dst[0] = make_float4(f0.x, f0.y, f1.x, f1.y);
        dst[1] = make_float4(f2.x, f2.y, f3.x, f3.y);
    }
    __syncwarp();

    float s[32];
    unsigned long long NS[16];

    for (int m = 0; m < MM; ++m) {
        // prefetch next mode's margins (global, bf16)
        if (m < MM - 1) {
            #pragma unroll
            for (int k = 0; k < 4; ++k)
                w[k] = __ldg(gsrc + (m + 1) * 128 + lane * 4 + k);
        }

        if (m == 0) {
            // init: lane l takes state row l = M0 row l
            const float4* r = reinterpret_cast<const float4*>(&Mst[lane * CH_STR]);
            #pragma unroll
            for (int k = 0; k < 8; ++k) {
                float4 v = r[k];
                s[4 * k] = v.x; s[4 * k + 1] = v.y;
                s[4 * k + 2] = v.z; s[4 * k + 3] = v.w;
            }
        } else {
            #pragma unroll
            for (int k = 0; k < 16; ++k) NS[k] = 0ull;
            #pragma unroll
            for (int j = 0; j < RR; ++j) {
                const unsigned long long mj = splat2(s[j]);
                const ulonglong2* mr =
                    reinterpret_cast<const ulonglong2*>(&Mst[j * CH_STR]);
                #pragma unroll
                for (int k = 0; k < 8; ++k) {
                    ulonglong2 mv = mr[k];   // broadcast: all lanes same addr
                    fma2(NS[2 * k], mj, mv.x);
                    fma2(NS[2 * k + 1], mj, mv.y);
                }
            }
            #pragma unroll
            for (int k = 0; k < 16; ++k) unpack2(NS[k], s[2 * k], s[2 * k + 1]);
        }
        __syncwarp();   // all broadcast reads done before restage

        if (m < MM - 1) {
            #pragma unroll
            for (int k = 0; k < 4; ++k) {
                const __nv_bfloat162* h = reinterpret_cast<const __nv_bfloat162*>(&w[k]);
                float2 f0 = __bfloat1622float2(h[0]);
                float2 f1 = __bfloat1622float2(h[1]);
                float2 f2 = __bfloat1622float2(h[2]);
                float2 f3 = __bfloat1622float2(h[3]);
                float4* dst = reinterpret_cast<float4*>(&Mst[lane * CH_STR + k * 8]);
                dst[0] = make_float4(f0.x, f0.y, f1.x, f1.y);
                dst[1] = make_float4(f2.x, f2.y, f3.x, f3.y);
            }
            __syncwarp();
        }
    }

    // epilogue: dump state rows, read diagonal, reduce, log
    {
        float4* dst = reinterpret_cast<float4*>(&Mst[lane * CH_STR]);
        #pragma unroll
        for (int k = 0; k < 8; ++k)
            dst[k] = make_float4(s[4 * k], s[4 * k + 1], s[4 * k + 2], s[4 * k + 3]);
        __syncwarp();
        float dv = Mst[lane * CH_STR + lane];
        #pragma unroll
        for (int o = 16; o > 0; o >>= 1) dv += __shfl_xor_sync(0xffffffffu, dv, o);
        if (lane == 0)
            out[b] = logf(fmaxf(dv, 1e-12f)) - g_lognorm;
    }
}

// ---------------- launch ----------------
extern "C" void kernel_launch(void* const* d_in, const int* in_sizes, int n_in,
                              void* d_out, int out_size) {
    const float* value     = (const float*)d_in[0];  // (B, M)
    const float* location  = (const float*)d_in[1];  // (D, M)
    const float* log_scale = (const float*)d_in[2];  // (D, M)
    const float* cores     = (const float*)d_in[3];  // (M, D, R, R)
    float* out = (float*)d_out;

    const int B = in_sizes[0] / MM;   // 32768

    k_prep<<<(MM * 4 * 8 * 16 * 2 * 32) / 256, 256>>>(cores);
    k_modesum<<<MM, 1024>>>(cores);
    k_normchain<<<1, 1024>>>();

    static bool attr_done = false;
    if (!attr_done) {
        cudaFuncSetAttribute(k_margins,
                             cudaFuncAttributeMaxDynamicSharedMemorySize, M_SMEM);
        cudaFuncSetAttribute(k_chain,
                             cudaFuncAttributeMaxDynamicSharedMemorySize, C_SMEM);
        attr_done = true;
    }

    k_margins<<<(B / MT) * MM, 512, M_SMEM>>>(value, location, log_scale);
    k_chain<<<B / 8, 256, C_SMEM>>>(out);
}

// round 10
// speedup vs baseline: 4.4852x; 1.0285x over previous
#include <cuda_runtime.h>
#include <cuda_bf16.h>
#include <cstdint>

// Problem constants (TRIP log_prob): B=32768, M=8, D=256, R=32
#define MM 8
#define DD 256
#define RR 32
#define NN (RR * RR)          // 1024
#define MT 128                // batch rows per margin block
#define BTOT 32768

#define LOG_2PI_F 1.8378770664093453f

// ---------------- global scratch ----------------
// B fragments pre-permuted for mma.sync m16n8k16:
// uint4 index u = ((((mode*4+ni)*8 + g)*16 + kstep)*2 + half)*32 + lane
// components: c32 = (ntile&1)*2 + isb1, bf16 slot = k parity; ntile = half*2 + (c32>>1)
__device__ uint4 g_bf4[MM * 4 * 8 * 16 * 2 * 32];         // 4 MB
__device__ __nv_bfloat16 g_marg[(size_t)BTOT * MM * NN];  // 512 MB margins [b][mode][n]
__device__ float g_s[MM * NN];                            // per-mode core sums (f32)
__device__ float g_lognorm;

// ---------------- helpers ----------------
__device__ __forceinline__ float softplus_f(float x) {
    return (x > 20.0f) ? x : log1pf(expf(x));
}
__device__ __forceinline__ unsigned long long splat2(float x) {
    unsigned long long r;
    asm("mov.b64 %0, {%1, %1};" : "=l"(r) : "f"(x));
    return r;
}
__device__ __forceinline__ void fma2(unsigned long long& acc,
                                     unsigned long long a,
                                     unsigned long long b) {
    asm("fma.rn.f32x2 %0, %1, %2, %0;" : "+l"(acc) : "l"(a), "l"(b));
}
__device__ __forceinline__ void unpack2(unsigned long long v, float& lo, float& hi) {
    asm("mov.b64 {%0, %1}, %2;" : "=f"(lo), "=f"(hi) : "l"(v));
}
__device__ __forceinline__ uint32_t bf2_bits(float a, float b) {
    __nv_bfloat162 h = __floats2bfloat162_rn(a, b);  // .x=a (low), .y=b (high)
    return *reinterpret_cast<uint32_t*>(&h);
}
__device__ __forceinline__ uint32_t smem_u32(const void* p) {
    uint32_t a;
    asm("{ .reg .u64 t; cvta.to.shared.u64 t, %1; cvt.u32.u64 %0, t; }" : "=r"(a) : "l"(p));
    return a;
}
__device__ __forceinline__ void ldsm4(uint32_t& r0, uint32_t& r1,
                                      uint32_t& r2, uint32_t& r3, uint32_t addr) {
    asm volatile("ldmatrix.sync.aligned.m8n8.x4.shared.b16 {%0,%1,%2,%3}, [%4];"
                 : "=r"(r0), "=r"(r1), "=r"(r2), "=r"(r3) : "r"(addr));
}
__device__ __forceinline__ void mma_bf16(float* d, const uint32_t* a,
                                         uint32_t b0, uint32_t b1) {
    asm volatile(
        "mma.sync.aligned.m16n8k16.row.col.f32.bf16.bf16.f32 "
        "{%0,%1,%2,%3}, {%4,%5,%6,%7}, {%8,%9}, {%0,%1,%2,%3};"
        : "+f"(d[0]), "+f"(d[1]), "+f"(d[2]), "+f"(d[3])
        : "r"(a[0]), "r"(a[1]), "r"(a[2]), "r"(a[3]), "r"(b0), "r"(b1));
}
// swizzled smem address: rows of 512B (256 bf16), 16B chunk XOR (row&7)
__device__ __forceinline__ uint32_t swz(uint32_t base, int row, int chunk) {
    return base + row * 512 + (((chunk) ^ (row & 7)) << 4);
}

// ---------------- kernel: prep  softplus(cores) -> B fragments ----------------
__global__ void k_prep(const float* __restrict__ cores) {
    int u = blockIdx.x * blockDim.x + threadIdx.x;  // 262144
    int lane = u & 31;
    int half = (u >> 5) & 1;
    int ks = (u >> 6) & 15;
    int g = (u >> 10) & 7;
    int ni = (u >> 13) & 3;
    int mode = u >> 15;
    int ncol = lane >> 2, tig = lane & 3;

    uint4 out;
    uint32_t comp[4];
    #pragma unroll
    for (int c32 = 0; c32 < 4; ++c32) {
        int ntile = half * 2 + (c32 >> 1);
        int isb1 = c32 & 1;
        int n = g * 128 + ni * 32 + ntile * 8 + ncol;
        int d = ks * 16 + isb1 * 8 + tig * 2;
        size_t base = (size_t)mode * (DD * NN) + (size_t)d * NN + n;
        float x0 = __ldg(&cores[base]);
        float x1 = __ldg(&cores[base + NN]);   // d+1
        comp[c32] = bf2_bits(softplus_f(x0), softplus_f(x1));
    }
    out.x = comp[0]; out.y = comp[1]; out.z = comp[2]; out.w = comp[3];
    g_bf4[u] = out;
}

// ---------------- kernel: per-mode core sums (f32, straight from cores) ----------------
__global__ void k_modesum(const float* __restrict__ cores) {  // grid = MM, 1024 thr
    int mode = blockIdx.x;
    int t = threadIdx.x;  // n = 32j + c
    float a = 0.0f;
    const float* base = cores + (size_t)mode * (DD * NN) + t;
    #pragma unroll 4
    for (int d = 0; d < DD; ++d) a += softplus_f(base[(size_t)d * NN]);
    g_s[mode * NN + t] = a;
}

// ---------------- kernel: norm chain + log(trace) ----------------
__global__ void k_normchain() {  // 1 block, 1024 threads
    __shared__ float nrm[NN];
    __shared__ float s[NN];
    __shared__ float tmp[NN];
    int t = threadIdx.x;
    int r = t >> 5, c = t & 31;
    nrm[t] = g_s[t];
    __syncthreads();
    for (int i = 1; i < MM; ++i) {
        s[t] = g_s[i * NN + t];
        __syncthreads();
        float a = 0.0f;
        #pragma unroll
        for (int j = 0; j < RR; ++j) a += nrm[r * RR + j] * s[j * RR + c];
        tmp[t] = a;
        __syncthreads();
        nrm[t] = tmp[t];
        __syncthreads();
    }
    if (t == 0) {
        float tr = 0.0f;
        #pragma unroll
        for (int k = 0; k < RR; ++k) tr += nrm[k * (RR + 1)];
        g_lognorm = logf(tr);
    }
}

// ---------------- kernel: margins (HMMA m64xn32 warp tiles) ----------------
// grid = (B/128)*8, mode = bx>>8. 16 warps = 2(m-half of 64 rows) x 8(n).
// Warp covers cols cg*256 + nj*32 over cg=0..3. SMEM: A = E[128][256] bf16 (64KB).
#define M_SMEM 65536

__global__ void __launch_bounds__(512, 1)
k_margins(const float* __restrict__ value,
          const float* __restrict__ location,
          const float* __restrict__ log_scale) {
    extern __shared__ unsigned char sm[];
    __shared__ float sloc[DD], sinv[DD], scb[DD];

    const uint32_t aA = smem_u32(sm);
    const int tid = threadIdx.x;
    const int wid = tid >> 5;
    const int lane = tid & 31;
    const int mode = blockIdx.x >> 8;
    const int bblk = (blockIdx.x & 255) * MT;

    if (tid < DD) {
        float lsi = __ldg(&log_scale[tid * MM + mode]);
        sloc[tid] = __ldg(&location[tid * MM + mode]);
        sinv[tid] = __expf(-lsi);
        scb[tid] = -0.5f * LOG_2PI_F - lsi;
    }
    __syncthreads();

    // ---- E tile: Gaussian weights bf16 into swizzled A smem ----
    {
        const int b = tid >> 2;     // batch row 0..127
        const int quad = tid & 3;   // d-range quad*64..+63
        const float v = __ldg(&value[(size_t)(bblk + b) * MM + mode]);
        #pragma unroll
        for (int dd = 0; dd < 64; dd += 2) {
            const int d = quad * 64 + dd;
            float z0 = (v - sloc[d]) * sinv[d];
            float p0 = __expf(fmaf(-0.5f * z0, z0, scb[d]));
            float z1 = (v - sloc[d + 1]) * sinv[d + 1];
            float p1 = __expf(fmaf(-0.5f * z1, z1, scb[d + 1]));
            uint32_t addr = swz(aA, b, d >> 3) + (d & 7) * 2;
            asm volatile("st.shared.b32 [%0], %1;" :: "r"(addr), "r"(bf2_bits(p0, p1)));
        }
    }
    __syncthreads();

    // ---- warp tiling: mi2 = m-half (64 rows), nj = n-slot (32 cols per cg) ----
    const int mi2 = wid & 1;
    const int nj = wid >> 1;       // 0..7
    const int njh = nj >> 2;       // high bit -> g offset
    const int a_row = mi2 * 64 + (lane & 7) + ((lane >> 3) & 1) * 8;
    const int a_cad = lane >> 4;

    // B fragment base for this warp's ni = nj&3
    const uint4* __restrict__ bbase =
        g_bf4 + (size_t)((mode * 4 + (nj & 3)) * 8192) + lane;

    // flat step t = cg*16 + ks (0..63); uint4 offset for step t:
    //   (( (t>>4)*2 + njh )*16 + (t&15)) * 64   (+32 for half 1)
    #define BOFF(t) ((size_t)(((((t) >> 4) * 2 + njh) * 16 + ((t) & 15)) * 64))

    // distance-2 prefetch pipeline
    uint4 P0 = __ldg(bbase + BOFF(0)), P1 = __ldg(bbase + BOFF(0) + 32);
    uint4 Q0 = __ldg(bbase + BOFF(1)), Q1 = __ldg(bbase + BOFF(1) + 32);

    for (int cg = 0; cg < 4; ++cg) {
        float acc[4][4][4];
        #pragma unroll
        for (int mt = 0; mt < 4; ++mt)
            #pragma unroll
            for (int nt = 0; nt < 4; ++nt)
                #pragma unroll
                for (int e = 0; e < 4; ++e) acc[mt][nt][e] = 0.0f;

        #pragma unroll
        for (int ks = 0; ks < 16; ++ks) {
            int t = cg * 16 + ks + 2;
            t = (t > 63) ? 63 : t;
            uint4 R0 = __ldg(bbase + BOFF(t));
            uint4 R1 = __ldg(bbase + BOFF(t) + 32);

            uint32_t a[4][4];
            #pragma unroll
            for (int mt = 0; mt < 4; ++mt)
                ldsm4(a[mt][0], a[mt][1], a[mt][2], a[mt][3],
                      swz(aA, a_row + mt * 16, 2 * ks + a_cad));

            #pragma unroll
            for (int mt = 0; mt < 4; ++mt) {
                mma_bf16(acc[mt][0], a[mt], P0.x, P0.y);
                mma_bf16(acc[mt][1], a[mt], P0.z, P0.w);
                mma_bf16(acc[mt][2], a[mt], P1.x, P1.y);
                mma_bf16(acc[mt][3], a[mt], P1.z, P1.w);
            }
            P0 = Q0; P1 = Q1; Q0 = R0; Q1 = R1;
        }

        // ---- store margins bf16 (fragment layout: row=l/4(+8), col=2(l%4)) ----
        #pragma unroll
        for (int mt = 0; mt < 4; ++mt) {
            const int row = bblk + mi2 * 64 + mt * 16 + (lane >> 2);
            #pragma unroll
            for (int nt = 0; nt < 4; ++nt) {
                const int col = cg * 256 + nj * 32 + nt * 8 + 2 * (lane & 3);
                uint32_t lo = bf2_bits(acc[mt][nt][0], acc[mt][nt][1]);
                uint32_t hi = bf2_bits(acc[mt][nt][2], acc[mt][nt][3]);
                *reinterpret_cast<uint32_t*>(
                    &g_marg[((size_t)row * MM + mode) * NN + col]) = lo;
                *reinterpret_cast<uint32_t*>(
                    &g_marg[((size_t)(row + 8) * MM + mode) * NN + col]) = hi;
            }
        }
    }
    #undef BOFF
}

// ---------------- kernel: chain (state rows in registers, M rows broadcast) ----------------
#define CH_STR 40
#define C_SMEM (8 * 32 * CH_STR * 4)   // 40960 B

__global__ void __launch_bounds__(256, 2)
k_chain(float* __restrict__ out) {
    extern __shared__ float Mst_all[];
    const int tid = threadIdx.x;
    const int wid = tid >> 5;
    const int lane = tid & 31;
    const int b = blockIdx.x * 8 + wid;

    float* Mst = Mst_all + wid * (32 * CH_STR);
    const uint4* __restrict__ gsrc =
        reinterpret_cast<const uint4*>(g_marg) + (size_t)b * MM * 128;

    uint4 w[4];
    #pragma unroll
    for (int k = 0; k < 4; ++k) w[k] = __ldg(gsrc + lane * 4 + k);
    #pragma unroll
    for (int k = 0; k < 4; ++k) {
        const __nv_bfloat162* h = reinterpret_cast<const __nv_bfloat162*>(&w[k]);
        float2 f0 = __bfloat1622float2(h[0]);
        float2 f1 = __bfloat1622float2(h[1]);
        float2 f2 = __bfloat1622float2(h[2]);
        float2 f3 = __bfloat1622float2(h[3]);
        float4* dst = reinterpret_cast<float4*>(&Mst[lane * CH_STR + k * 8]);
        dst[0] = make_float4(f0.x, f0.y, f1.x, f1.y);
        dst[1] = make_float4(f2.x, f2.y, f3.x, f3.y);
    }
    __syncwarp();

    float s[32];
    unsigned long long NS[16];

    for (int m = 0; m < MM; ++m) {
        if (m < MM - 1) {
            #pragma unroll
            for (int k = 0; k < 4; ++k)
                w[k] = __ldg(gsrc + (m + 1) * 128 + lane * 4 + k);
        }

        if (m == 0) {
            const float4* r = reinterpret_cast<const float4*>(&Mst[lane * CH_STR]);
            #pragma unroll
            for (int k = 0; k < 8; ++k) {
                float4 v = r[k];
                s[4 * k] = v.x; s[4 * k + 1] = v.y;
                s[4 * k + 2] = v.z; s[4 * k + 3] = v.w;
            }
        } else {
            #pragma unroll
            for (int k = 0; k < 16; ++k) NS[k] = 0ull;
            #pragma unroll
            for (int j = 0; j < RR; ++j) {
                const unsigned long long mj = splat2(s[j]);
                const ulonglong2* mr =
                    reinterpret_cast<const ulonglong2*>(&Mst[j * CH_STR]);
                #pragma unroll
                for (int k = 0; k < 8; ++k) {
                    ulonglong2 mv = mr[k];   // broadcast
                    fma2(NS[2 * k], mj, mv.x);
                    fma2(NS[2 * k + 1], mj, mv.y);
                }
            }
            #pragma unroll
            for (int k = 0; k < 16; ++k) unpack2(NS[k], s[2 * k], s[2 * k + 1]);
        }
        __syncwarp();

        if (m < MM - 1) {
            #pragma unroll
            for (int k = 0; k < 4; ++k) {
                const __nv_bfloat162* h = reinterpret_cast<const __nv_bfloat162*>(&w[k]);
                float2 f0 = __bfloat1622float2(h[0]);
                float2 f1 = __bfloat1622float2(h[1]);
                float2 f2 = __bfloat1622float2(h[2]);
                float2 f3 = __bfloat1622float2(h[3]);
                float4* dst = reinterpret_cast<float4*>(&Mst[lane * CH_STR + k * 8]);
                dst[0] = make_float4(f0.x, f0.y, f1.x, f1.y);
                dst[1] = make_float4(f2.x, f2.y, f3.x, f3.y);
            }
            __syncwarp();
        }
    }

    {
        float4* dst = reinterpret_cast<float4*>(&Mst[lane * CH_STR]);
        #pragma unroll
        for (int k = 0; k < 8; ++k)
            dst[k] = make_float4(s[4 * k], s[4 * k + 1], s[4 * k + 2], s[4 * k + 3]);
        __syncwarp();
        float dv = Mst[lane * CH_STR + lane];
        #pragma unroll
        for (int o = 16; o > 0; o >>= 1) dv += __shfl_xor_sync(0xffffffffu, dv, o);
        if (lane == 0)
            out[b] = logf(fmaxf(dv, 1e-12f)) - g_lognorm;
    }
}

// ---------------- launch ----------------
extern "C" void kernel_launch(void* const* d_in, const int* in_sizes, int n_in,
                              void* d_out, int out_size) {
    const float* value     = (const float*)d_in[0];  // (B, M)
    const float* location  = (const float*)d_in[1];  // (D, M)
    const float* log_scale = (const float*)d_in[2];  // (D, M)
    const float* cores     = (const float*)d_in[3];  // (M, D, R, R)
    float* out = (float*)d_out;

    const int B = in_sizes[0] / MM;   // 32768

    k_prep<<<(MM * 4 * 8 * 16 * 2 * 32) / 256, 256>>>(cores);
    k_modesum<<<MM, 1024>>>(cores);
    k_normchain<<<1, 1024>>>();

    static bool attr_done = false;
    if (!attr_done) {
        cudaFuncSetAttribute(k_margins,
                             cudaFuncAttributeMaxDynamicSharedMemorySize, M_SMEM);
        cudaFuncSetAttribute(k_chain,
                             cudaFuncAttributeMaxDynamicSharedMemorySize, C_SMEM);
        attr_done = true;
    }

    k_margins<<<(B / MT) * MM, 512, M_SMEM>>>(value, location, log_scale);
    k_chain<<<B / 8, 256, C_SMEM>>>(out);
}

// round 11
// speedup vs baseline: 7.3022x; 1.6281x over previous
#include <cuda_runtime.h>
#include <cuda_bf16.h>
#include <cstdint>

// Problem constants (TRIP log_prob): B=32768, M=8, D=256, R=32
#define MM 8
#define DD 256
#define RR 32
#define NN (RR * RR)          // 1024
#define MT 128                // batch rows per margin block
#define BTOT 32768

#define LOG_2PI_F 1.8378770664093453f

// ---------------- global scratch ----------------
// B fragments pre-permuted for mma.sync m16n8k16 (margins GEMM):
// uint4 index u = ((((mode*4+ni)*8 + g)*16 + kstep)*2 + half)*32 + lane
__device__ uint4 g_bf4[MM * 4 * 8 * 16 * 2 * 32];         // 4 MB
__device__ __nv_bfloat16 g_marg[(size_t)BTOT * MM * NN];  // 512 MB margins [b][mode][n]
__device__ float g_s[MM * NN];                            // per-mode core sums (f32)
__device__ float g_lognorm;

// ---------------- helpers ----------------
__device__ __forceinline__ float softplus_f(float x) {
    return (x > 20.0f) ? x : log1pf(expf(x));
}
__device__ __forceinline__ uint32_t bf2_bits(float a, float b) {
    __nv_bfloat162 h = __floats2bfloat162_rn(a, b);  // .x=a (low), .y=b (high)
    return *reinterpret_cast<uint32_t*>(&h);
}
__device__ __forceinline__ uint32_t smem_u32(const void* p) {
    uint32_t a;
    asm("{ .reg .u64 t; cvta.to.shared.u64 t, %1; cvt.u32.u64 %0, t; }" : "=r"(a) : "l"(p));
    return a;
}
__device__ __forceinline__ void ldsm4(uint32_t& r0, uint32_t& r1,
                                      uint32_t& r2, uint32_t& r3, uint32_t addr) {
    asm volatile("ldmatrix.sync.aligned.m8n8.x4.shared.b16 {%0,%1,%2,%3}, [%4];"
                 : "=r"(r0), "=r"(r1), "=r"(r2), "=r"(r3) : "r"(addr));
}
__device__ __forceinline__ void ldsm4_trans(uint32_t& r0, uint32_t& r1,
                                            uint32_t& r2, uint32_t& r3, uint32_t addr) {
    asm volatile("ldmatrix.sync.aligned.m8n8.x4.trans.shared.b16 {%0,%1,%2,%3}, [%4];"
                 : "=r"(r0), "=r"(r1), "=r"(r2), "=r"(r3) : "r"(addr));
}
__device__ __forceinline__ void mma_bf16(float* d, const uint32_t* a,
                                         uint32_t b0, uint32_t b1) {
    asm volatile(
        "mma.sync.aligned.m16n8k16.row.col.f32.bf16.bf16.f32 "
        "{%0,%1,%2,%3}, {%4,%5,%6,%7}, {%8,%9}, {%0,%1,%2,%3};"
        : "+f"(d[0]), "+f"(d[1]), "+f"(d[2]), "+f"(d[3])
        : "r"(a[0]), "r"(a[1]), "r"(a[2]), "r"(a[3]), "r"(b0), "r"(b1));
}
__device__ __forceinline__ void cp_async16(uint32_t smem_addr, const void* gptr) {
    asm volatile("cp.async.cg.shared.global [%0], [%1], 16;"
                 :: "r"(smem_addr), "l"(gptr) : "memory");
}
__device__ __forceinline__ void cp_commit() {
    asm volatile("cp.async.commit_group;" ::: "memory");
}
template <int N>
__device__ __forceinline__ void cp_wait() {
    asm volatile("cp.async.wait_group %0;" :: "n"(N) : "memory");
}
// swizzled smem address: rows of 512B (256 bf16), 16B chunk XOR (row&7)
__device__ __forceinline__ uint32_t swz(uint32_t base, int row, int chunk) {
    return base + row * 512 + (((chunk) ^ (row & 7)) << 4);
}

// ---------------- kernel: prep  softplus(cores) -> B fragments ----------------
__global__ void k_prep(const float* __restrict__ cores) {
    int u = blockIdx.x * blockDim.x + threadIdx.x;  // 262144
    int lane = u & 31;
    int half = (u >> 5) & 1;
    int ks = (u >> 6) & 15;
    int g = (u >> 10) & 7;
    int ni = (u >> 13) & 3;
    int mode = u >> 15;
    int ncol = lane >> 2, tig = lane & 3;

    uint4 out;
    uint32_t comp[4];
    #pragma unroll
    for (int c32 = 0; c32 < 4; ++c32) {
        int ntile = half * 2 + (c32 >> 1);
        int isb1 = c32 & 1;
        int n = g * 128 + ni * 32 + ntile * 8 + ncol;
        int d = ks * 16 + isb1 * 8 + tig * 2;
        size_t base = (size_t)mode * (DD * NN) + (size_t)d * NN + n;
        float x0 = __ldg(&cores[base]);
        float x1 = __ldg(&cores[base + NN]);   // d+1
        comp[c32] = bf2_bits(softplus_f(x0), softplus_f(x1));
    }
    out.x = comp[0]; out.y = comp[1]; out.z = comp[2]; out.w = comp[3];
    g_bf4[u] = out;
}

// ---------------- kernel: per-mode core sums (f32, straight from cores) ----------------
__global__ void k_modesum(const float* __restrict__ cores) {  // grid = MM, 1024 thr
    int mode = blockIdx.x;
    int t = threadIdx.x;  // n = 32j + c
    float a = 0.0f;
    const float* base = cores + (size_t)mode * (DD * NN) + t;
    #pragma unroll 4
    for (int d = 0; d < DD; ++d) a += softplus_f(base[(size_t)d * NN]);
    g_s[mode * NN + t] = a;
}

// ---------------- kernel: norm chain + log(trace) ----------------
__global__ void k_normchain() {  // 1 block, 1024 threads
    __shared__ float nrm[NN];
    __shared__ float s[NN];
    __shared__ float tmp[NN];
    int t = threadIdx.x;
    int r = t >> 5, c = t & 31;
    nrm[t] = g_s[t];
    __syncthreads();
    for (int i = 1; i < MM; ++i) {
        s[t] = g_s[i * NN + t];
        __syncthreads();
        float a = 0.0f;
        #pragma unroll
        for (int j = 0; j < RR; ++j) a += nrm[r * RR + j] * s[j * RR + c];
        tmp[t] = a;
        __syncthreads();
        nrm[t] = tmp[t];
        __syncthreads();
    }
    if (t == 0) {
        float tr = 0.0f;
        #pragma unroll
        for (int k = 0; k < RR; ++k) tr += nrm[k * (RR + 1)];
        g_lognorm = logf(tr);
    }
}

// ---------------- kernel: margins (HMMA m64xn32 warp tiles) ----------------
// grid = (B/128)*8, mode = bx>>8. 16 warps = 2(m-half of 64 rows) x 8(n).
#define M_SMEM 65536

__global__ void __launch_bounds__(512, 1)
k_margins(const float* __restrict__ value,
          const float* __restrict__ location,
          const float* __restrict__ log_scale) {
    extern __shared__ unsigned char sm[];
    __shared__ float sloc[DD], sinv[DD], scb[DD];

    const uint32_t aA = smem_u32(sm);
    const int tid = threadIdx.x;
    const int wid = tid >> 5;
    const int lane = tid & 31;
    const int mode = blockIdx.x >> 8;
    const int bblk = (blockIdx.x & 255) * MT;

    if (tid < DD) {
        float lsi = __ldg(&log_scale[tid * MM + mode]);
        sloc[tid] = __ldg(&location[tid * MM + mode]);
        sinv[tid] = __expf(-lsi);
        scb[tid] = -0.5f * LOG_2PI_F - lsi;
    }
    __syncthreads();

    // ---- E tile: Gaussian weights bf16 into swizzled A smem ----
    {
        const int b = tid >> 2;     // batch row 0..127
        const int quad = tid & 3;   // d-range quad*64..+63
        const float v = __ldg(&value[(size_t)(bblk + b) * MM + mode]);
        #pragma unroll
        for (int dd = 0; dd < 64; dd += 2) {
            const int d = quad * 64 + dd;
            float z0 = (v - sloc[d]) * sinv[d];
            float p0 = __expf(fmaf(-0.5f * z0, z0, scb[d]));
            float z1 = (v - sloc[d + 1]) * sinv[d + 1];
            float p1 = __expf(fmaf(-0.5f * z1, z1, scb[d + 1]));
            uint32_t addr = swz(aA, b, d >> 3) + (d & 7) * 2;
            asm volatile("st.shared.b32 [%0], %1;" :: "r"(addr), "r"(bf2_bits(p0, p1)));
        }
    }
    __syncthreads();

    const int mi2 = wid & 1;
    const int nj = wid >> 1;       // 0..7
    const int njh = nj >> 2;
    const int a_row = mi2 * 64 + (lane & 7) + ((lane >> 3) & 1) * 8;
    const int a_cad = lane >> 4;

    const uint4* __restrict__ bbase =
        g_bf4 + (size_t)((mode * 4 + (nj & 3)) * 8192) + lane;

    #define BOFF(t) ((size_t)(((((t) >> 4) * 2 + njh) * 16 + ((t) & 15)) * 64))

    uint4 P0 = __ldg(bbase + BOFF(0)), P1 = __ldg(bbase + BOFF(0) + 32);
    uint4 Q0 = __ldg(bbase + BOFF(1)), Q1 = __ldg(bbase + BOFF(1) + 32);

    for (int cg = 0; cg < 4; ++cg) {
        float acc[4][4][4];
        #pragma unroll
        for (int mt = 0; mt < 4; ++mt)
            #pragma unroll
            for (int nt = 0; nt < 4; ++nt)
                #pragma unroll
                for (int e = 0; e < 4; ++e) acc[mt][nt][e] = 0.0f;

        #pragma unroll
        for (int ks = 0; ks < 16; ++ks) {
            int t = cg * 16 + ks + 2;
            t = (t > 63) ? 63 : t;
            uint4 R0 = __ldg(bbase + BOFF(t));
            uint4 R1 = __ldg(bbase + BOFF(t) + 32);

            uint32_t a[4][4];
            #pragma unroll
            for (int mt = 0; mt < 4; ++mt)
                ldsm4(a[mt][0], a[mt][1], a[mt][2], a[mt][3],
                      swz(aA, a_row + mt * 16, 2 * ks + a_cad));

            #pragma unroll
            for (int mt = 0; mt < 4; ++mt) {
                mma_bf16(acc[mt][0], a[mt], P0.x, P0.y);
                mma_bf16(acc[mt][1], a[mt], P0.z, P0.w);
                mma_bf16(acc[mt][2], a[mt], P1.x, P1.y);
                mma_bf16(acc[mt][3], a[mt], P1.z, P1.w);
            }
            P0 = Q0; P1 = Q1; Q0 = R0; Q1 = R1;
        }

        #pragma unroll
        for (int mt = 0; mt < 4; ++mt) {
            const int row = bblk + mi2 * 64 + mt * 16 + (lane >> 2);
            #pragma unroll
            for (int nt = 0; nt < 4; ++nt) {
                const int col = cg * 256 + nj * 32 + nt * 8 + 2 * (lane & 3);
                uint32_t lo = bf2_bits(acc[mt][nt][0], acc[mt][nt][1]);
                uint32_t hi = bf2_bits(acc[mt][nt][2], acc[mt][nt][3]);
                *reinterpret_cast<uint32_t*>(
                    &g_marg[((size_t)row * MM + mode) * NN + col]) = lo;
                *reinterpret_cast<uint32_t*>(
                    &g_marg[((size_t)(row + 8) * MM + mode) * NN + col]) = hi;
            }
        }
    }
    #undef BOFF
}

// ---------------- kernel: chain via HMMA, state in D-fragments ----------------
// One warp = one batch; 16 warps/block; grid = B/16 = 2048.
// Per-warp smem: double-buffered margin [32 rows][80B stride] = 2x2560B.
#define CH_BUF 2560
#define C_SMEM (16 * 2 * CH_BUF)   // 81920

__global__ void __launch_bounds__(512, 2)
k_chain(float* __restrict__ out) {
    extern __shared__ unsigned char sm[];
    const int tid = threadIdx.x;
    const int wid = tid >> 5;
    const int lane = tid & 31;
    const int b = blockIdx.x * 16 + wid;

    unsigned char* buf = sm + wid * (2 * CH_BUF);
    const uint32_t abuf = smem_u32(buf);
    const char* gsrc = (const char*)(g_marg + (size_t)b * MM * NN);

    // prefetch mode 0 -> buf0, mode 1 -> buf1 (2 KB each, coalesced per warp)
    #pragma unroll
    for (int k = 0; k < 4; ++k) {
        int q = lane + 32 * k;
        cp_async16(abuf + (q >> 2) * 80 + (q & 3) * 16, gsrc + q * 16);
    }
    cp_commit();
    #pragma unroll
    for (int k = 0; k < 4; ++k) {
        int q = lane + 32 * k;
        cp_async16(abuf + CH_BUF + (q >> 2) * 80 + (q & 3) * 16, gsrc + 2048 + q * 16);
    }
    cp_commit();

    cp_wait<1>();
    __syncwarp();

    // init state D-fragments from mode-0 margin (buf0)
    float D[2][4][4];
    {
        const int r0 = lane >> 2, c0 = 2 * (lane & 3);
        #pragma unroll
        for (int mt = 0; mt < 2; ++mt)
            #pragma unroll
            for (int nt = 0; nt < 4; ++nt) {
                int r = 16 * mt + r0, c = 8 * nt + c0;
                __nv_bfloat162 v0 =
                    *reinterpret_cast<__nv_bfloat162*>(buf + r * 80 + c * 2);
                __nv_bfloat162 v1 =
                    *reinterpret_cast<__nv_bfloat162*>(buf + (r + 8) * 80 + c * 2);
                float2 f0 = __bfloat1622float2(v0);
                float2 f1 = __bfloat1622float2(v1);
                D[mt][nt][0] = f0.x; D[mt][nt][1] = f0.y;
                D[mt][nt][2] = f1.x; D[mt][nt][3] = f1.y;
            }
    }

    const int i8 = lane & 7, tsel = lane >> 3;

    for (int m = 1; m < MM; ++m) {
        // prefetch mode m+1 into the buffer holding mode m-1 (already consumed)
        if (m < MM - 1) {
            uint32_t dst = abuf + ((m + 1) & 1) * CH_BUF;
            const char* src = gsrc + (size_t)(m + 1) * 2048;
            #pragma unroll
            for (int k = 0; k < 4; ++k) {
                int q = lane + 32 * k;
                cp_async16(dst + (q >> 2) * 80 + (q & 3) * 16, src + q * 16);
            }
            cp_commit();
            cp_wait<1>();   // mode m's group complete; only m+1 may fly
        } else {
            cp_wait<0>();   // last mode: everything complete
        }
        __syncwarp();

        const uint32_t mb = abuf + (m & 1) * CH_BUF;

        // B fragments: 4 x ldmatrix.x4.trans (row-major M -> col.B operand)
        uint32_t B[2][4][2];  // [ks][nt][reg]
        #pragma unroll
        for (int ks = 0; ks < 2; ++ks)
            #pragma unroll
            for (int nh = 0; nh < 2; ++nh) {
                uint32_t addr = mb + (16 * ks + (tsel & 1) * 8 + i8) * 80 +
                                32 * nh + (tsel >> 1) * 16;
                uint32_t q0, q1, q2, q3;
                ldsm4_trans(q0, q1, q2, q3, addr);
                B[ks][2 * nh][0] = q0;     B[ks][2 * nh][1] = q1;
                B[ks][2 * nh + 1][0] = q2; B[ks][2 * nh + 1][1] = q3;
            }

        // A fragments from state D (D layout == A column layout)
        uint32_t A[2][2][4];  // [mt][ks][reg]
        #pragma unroll
        for (int mt = 0; mt < 2; ++mt)
            #pragma unroll
            for (int ks = 0; ks < 2; ++ks) {
                A[mt][ks][0] = bf2_bits(D[mt][2 * ks][0], D[mt][2 * ks][1]);
                A[mt][ks][1] = bf2_bits(D[mt][2 * ks][2], D[mt][2 * ks][3]);
                A[mt][ks][2] = bf2_bits(D[mt][2 * ks + 1][0], D[mt][2 * ks + 1][1]);
                A[mt][ks][3] = bf2_bits(D[mt][2 * ks + 1][2], D[mt][2 * ks + 1][3]);
            }

        #pragma unroll
        for (int mt = 0; mt < 2; ++mt)
            #pragma unroll
            for (int nt = 0; nt < 4; ++nt)
                #pragma unroll
                for (int e = 0; e < 4; ++e) D[mt][nt][e] = 0.0f;

        #pragma unroll
        for (int mt = 0; mt < 2; ++mt)
            #pragma unroll
            for (int nt = 0; nt < 4; ++nt)
                #pragma unroll
                for (int ks = 0; ks < 2; ++ks)
                    mma_bf16(D[mt][nt], A[mt][ks], B[ks][nt][0], B[ks][nt][1]);
    }

    // epilogue: trace of state from D fragments, warp reduce, log
    {
        float tr = 0.0f;
        const int r0 = lane >> 2, c0 = 2 * (lane & 3);
        #pragma unroll
        for (int mt = 0; mt < 2; ++mt)
            #pragma unroll
            for (int nt = 0; nt < 4; ++nt) {
                int rA = 16 * mt + r0, rB = rA + 8, c = 8 * nt + c0;
                if (c == rA)     tr += D[mt][nt][0];
                if (c + 1 == rA) tr += D[mt][nt][1];
                if (c == rB)     tr += D[mt][nt][2];
                if (c + 1 == rB) tr += D[mt][nt][3];
            }
        #pragma unroll
        for (int o = 16; o > 0; o >>= 1) tr += __shfl_xor_sync(0xffffffffu, tr, o);
        if (lane == 0)
            out[b] = logf(fmaxf(tr, 1e-12f)) - g_lognorm;
    }
}

// ---------------- launch ----------------
extern "C" void kernel_launch(void* const* d_in, const int* in_sizes, int n_in,
                              void* d_out, int out_size) {
    const float* value     = (const float*)d_in[0];  // (B, M)
    const float* location  = (const float*)d_in[1];  // (D, M)
    const float* log_scale = (const float*)d_in[2];  // (D, M)
    const float* cores     = (const float*)d_in[3];  // (M, D, R, R)
    float* out = (float*)d_out;

    const int B = in_sizes[0] / MM;   // 32768

    k_prep<<<(MM * 4 * 8 * 16 * 2 * 32) / 256, 256>>>(cores);
    k_modesum<<<MM, 1024>>>(cores);
    k_normchain<<<1, 1024>>>();

    static bool attr_done = false;
    if (!attr_done) {
        cudaFuncSetAttribute(k_margins,
                             cudaFuncAttributeMaxDynamicSharedMemorySize, M_SMEM);
        cudaFuncSetAttribute(k_chain,
                             cudaFuncAttributeMaxDynamicSharedMemorySize, C_SMEM);
        attr_done = true;
    }

    k_margins<<<(B / MT) * MM, 512, M_SMEM>>>(value, location, log_scale);
    k_chain<<<B / 16, 512, C_SMEM>>>(out);
}